// round 12
// baseline (speedup 1.0000x reference)
#include <cuda_runtime.h>
#include <cuda_fp16.h>
#include <math.h>
#include <cstdint>

// Problem dims (fixed by reference)
#define Bn  32
#define Ln  1024
#define Dn  512
#define Hn  8
#define DHn 64

#define NEGC (-4294967295.0f)   // -2^32 + 1, matches reference padding value
#define LOG2E 1.4426950408889634f

// ---------------------------------------------------------------------------
// Scratch (allocation-free rule: static __device__ globals)
// ---------------------------------------------------------------------------
__device__ float g_kmask[Bn * Ln];
__device__ float g_qmask[Bn * Ln];

#define NELEM_A ((size_t)Bn * Ln * Dn)      // 16,777,216
#define NELEM_W ((size_t)Dn * Dn)           // 262,144
__device__ __half g_qhi[NELEM_A];
__device__ __half g_qlo[NELEM_A];
__device__ __half g_khi[NELEM_A];
__device__ __half g_klo[NELEM_A];
__device__ __half g_whi[3][NELEM_W];
__device__ __half g_wlo[3][NELEM_W];

// Projected Q/K/V, fp16 hi/lo, head-major layout [b][h][l][64].
// z: 0 = Q (pre-scaled by log2e/8 for base-2 softmax), 1 = K, 2 = V (hi only)
__device__ __half g_prjh[3][NELEM_A];
__device__ __half g_prjl[3][NELEM_A];

// ---------------------------------------------------------------------------
// PTX helpers (sm_80-baseline only — tcgen05 does NOT assemble at .target
// sm_103 in this harness)
// ---------------------------------------------------------------------------
__device__ __forceinline__ uint32_t smem_u32(const void* p) {
    uint32_t a;
    asm("{ .reg .u64 t; cvta.to.shared.u64 t, %1; cvt.u32.u64 %0, t; }"
        : "=r"(a) : "l"(p));
    return a;
}
__device__ __forceinline__ void cp16(uint32_t dst, const void* src) {
    asm volatile("cp.async.cg.shared.global [%0], [%1], 16;\n"
                 :: "r"(dst), "l"(src) : "memory");
}
#define CP_COMMIT() asm volatile("cp.async.commit_group;\n" ::: "memory")

__device__ __forceinline__ void ldsm_x4(uint32_t* r, uint32_t addr) {
    asm volatile("ldmatrix.sync.aligned.m8n8.x4.shared.b16 {%0,%1,%2,%3}, [%4];"
                 : "=r"(r[0]), "=r"(r[1]), "=r"(r[2]), "=r"(r[3]) : "r"(addr));
}
__device__ __forceinline__ void ldsm_x4_t(uint32_t* r, uint32_t addr) {
    asm volatile("ldmatrix.sync.aligned.m8n8.x4.trans.shared.b16 {%0,%1,%2,%3}, [%4];"
                 : "=r"(r[0]), "=r"(r[1]), "=r"(r[2]), "=r"(r[3]) : "r"(addr));
}
__device__ __forceinline__ void mma16816(float* d, const uint32_t* a, const uint32_t* b) {
    asm volatile(
        "mma.sync.aligned.m16n8k16.row.col.f32.f16.f16.f32 "
        "{%0,%1,%2,%3}, {%4,%5,%6,%7}, {%8,%9}, {%0,%1,%2,%3};"
        : "+f"(d[0]), "+f"(d[1]), "+f"(d[2]), "+f"(d[3])
        : "r"(a[0]), "r"(a[1]), "r"(a[2]), "r"(a[3]), "r"(b[0]), "r"(b[1]));
}
__device__ __forceinline__ uint32_t pack_h2(float a, float b) {
    __half2 t = __floats2half2_rn(a, b);
    return *(uint32_t*)&t;
}
// Guaranteed single-MUFU base-2 exponential.
__device__ __forceinline__ float ex2(float x) {
    float y;
    asm("ex2.approx.f32 %0, %1;" : "=f"(y) : "f"(x));
    return y;
}

// ---------------------------------------------------------------------------
// Fused conversion + padding masks. One warp per 512-elem row.
// ---------------------------------------------------------------------------
__global__ void __launch_bounds__(256) cvt_all(const float* __restrict__ q,
                                               const float* __restrict__ k,
                                               const float* __restrict__ Wq,
                                               const float* __restrict__ Wk,
                                               const float* __restrict__ Wv) {
    int w = blockIdx.x * 8 + (threadIdx.x >> 5);
    int lane = threadIdx.x & 31;
    const float* src;
    __half *hi, *lo;
    float* maskp = nullptr;
    if (w < 65536) {
        int row = w & 32767;
        size_t off = (size_t)row * Dn;
        if (w < 32768) {
            src = q + off; hi = g_qhi + off; lo = g_qlo + off;
            maskp = g_qmask + row;
        } else {
            src = k + off; hi = g_khi + off; lo = g_klo + off;
            maskp = g_kmask + row;
        }
    } else {
        int r = w - 65536;
        int z = r >> 9, row = r & 511;
        size_t off = (size_t)row * Dn;
        src = (z == 0 ? Wq : (z == 1 ? Wk : Wv)) + off;
        hi = g_whi[z] + off; lo = g_wlo[z] + off;
    }
    float s = 0.f;
#pragma unroll
    for (int i = 0; i < 4; i++) {
        int f = lane + 32 * i;
        float4 v = ((const float4*)src)[f];
        s += (v.x + v.y) + (v.z + v.w);
        __half2 h0 = __floats2half2_rn(v.x, v.y);
        __half2 h1 = __floats2half2_rn(v.z, v.w);
        float2 f0 = __half22float2(h0);
        float2 f1 = __half22float2(h1);
        __half2 l0 = __floats2half2_rn(v.x - f0.x, v.y - f0.y);
        __half2 l1 = __floats2half2_rn(v.z - f1.x, v.w - f1.y);
        ((__half2*)hi)[2 * f + 0] = h0;
        ((__half2*)hi)[2 * f + 1] = h1;
        ((__half2*)lo)[2 * f + 0] = l0;
        ((__half2*)lo)[2 * f + 1] = l1;
    }
    if (maskp) {
#pragma unroll
        for (int o = 16; o; o >>= 1) s += __shfl_xor_sync(0xffffffffu, s, o);
        if (lane == 0) *maskp = (s != 0.0f) ? 1.0f : 0.0f;
    }
}

// ---------------------------------------------------------------------------
// fp16-split GEMM (mma.sync): proj_z = A_z @ W_z^T + bias_z -> fp16 hi/lo,
// head-major [b][h][l][64]; Q pre-scaled by log2e/8.
// z = 0 (Q), 1 (K): split-3 MMAs. z = 2 (V): SINGLE MMA (hi x hi).
// CTA tile 256x128, 8 warps, warp tile 64x64, K chunks of 32, 2-stage cp.async.
// ---------------------------------------------------------------------------
#define MATA   20480                 // 256 rows * 80B
#define MATW   10240                 // 128 rows * 80B
#define STAGE_B (2 * MATA + 2 * MATW)  // 61440
#define GEMM_SMEM (2 * STAGE_B)        // 122880

__device__ __forceinline__ void load_stage(uint32_t st,
                                           const __half* Ahi,
                                           const __half* Alo,
                                           const __half* Whi,
                                           const __half* Wlo,
                                           int bm, int bn, int kc, int tid,
                                           bool full) {
#pragma unroll
    for (int i = 0; i < 4; i++) {
        int idx = tid + 256 * i;            // 0..1023
        int row = idx >> 2, q4 = idx & 3;
        cp16(st + row * 80 + q4 * 16,
             Ahi + (size_t)(bm + row) * Dn + kc * 32 + q4 * 8);
    }
#pragma unroll
    for (int i = 0; i < 2; i++) {
        int idx = tid + 256 * i;            // 0..511
        int row = idx >> 2, q4 = idx & 3;
        cp16(st + 2 * MATA + row * 80 + q4 * 16,
             Whi + (size_t)(bn + row) * Dn + kc * 32 + q4 * 8);
    }
    if (full) {
#pragma unroll
        for (int i = 0; i < 4; i++) {
            int idx = tid + 256 * i;
            int row = idx >> 2, q4 = idx & 3;
            cp16(st + MATA + row * 80 + q4 * 16,
                 Alo + (size_t)(bm + row) * Dn + kc * 32 + q4 * 8);
        }
#pragma unroll
        for (int i = 0; i < 2; i++) {
            int idx = tid + 256 * i;
            int row = idx >> 2, q4 = idx & 3;
            cp16(st + 2 * MATA + MATW + row * 80 + q4 * 16,
                 Wlo + (size_t)(bn + row) * Dn + kc * 32 + q4 * 8);
        }
    }
    CP_COMMIT();
}

__global__ void __launch_bounds__(256, 1) gemm_mma(const float* __restrict__ bq,
                                                   const float* __restrict__ bk,
                                                   const float* __restrict__ bv) {
    extern __shared__ char smem_raw[];
    uint32_t sbase = smem_u32(smem_raw);
    int tid = threadIdx.x;
    int wid = tid >> 5, lane = tid & 31;
    int wm = wid & 3;
    int wn = wid >> 2;
    int z = blockIdx.z;
    int bn = blockIdx.x * 128;
    int bm = blockIdx.y * 256;
    bool full = (z != 2);             // V: single-MMA path

    const __half* Ahi = (z == 0) ? g_qhi : g_khi;
    const __half* Alo = (z == 0) ? g_qlo : g_klo;
    const __half* Whi = g_whi[z];
    const __half* Wlo = g_wlo[z];
    const float* bias = (z == 0) ? bq : (z == 1 ? bk : bv);
    float scale = (z == 0) ? (0.125f * LOG2E) : 1.0f;
    __half* Ohi = g_prjh[z];
    __half* Olo = g_prjl[z];

    float acc[4][8][4];
#pragma unroll
    for (int mt = 0; mt < 4; mt++)
#pragma unroll
        for (int nt = 0; nt < 8; nt++)
#pragma unroll
            for (int e = 0; e < 4; e++) acc[mt][nt][e] = 0.f;

    int a_row = lane & 15;
    int a_koff = (lane >> 4) * 16;
    int g = lane >> 3;
    int b_nadd = ((g >> 1) & 1) * 8 + (lane & 7);
    int b_kadd = (g & 1) * 8;

    load_stage(sbase, Ahi, Alo, Whi, Wlo, bm, bn, 0, tid, full);

#pragma unroll 1
    for (int s = 0; s < 16; s++) {
        if (s < 15) {
            load_stage(sbase + (uint32_t)((s + 1) & 1) * STAGE_B,
                       Ahi, Alo, Whi, Wlo, bm, bn, s + 1, tid, full);
            asm volatile("cp.async.wait_group 1;\n" ::: "memory");
        } else {
            asm volatile("cp.async.wait_group 0;\n" ::: "memory");
        }
        __syncthreads();
        uint32_t st = sbase + (uint32_t)(s & 1) * STAGE_B;

#pragma unroll
        for (int ks = 0; ks < 32; ks += 16) {
            uint32_t aH[4][4], aL[4][4], bH[8][2], bL[8][2];
#pragma unroll
            for (int mt = 0; mt < 4; mt++) {
                uint32_t ar = st + (uint32_t)((wm * 64 + mt * 16 + a_row) * 80)
                            + a_koff + ks * 2;
                ldsm_x4(aH[mt], ar);
                if (full) ldsm_x4(aL[mt], ar + MATA);
            }
#pragma unroll
            for (int ntp = 0; ntp < 4; ntp++) {
                uint32_t br = st + 2 * MATA
                            + (uint32_t)((wn * 64 + ntp * 16 + b_nadd) * 80)
                            + (ks + b_kadd) * 2;
                uint32_t t0[4], t1[4];
                ldsm_x4(t0, br);
                bH[2 * ntp][0] = t0[0]; bH[2 * ntp][1] = t0[1];
                bH[2 * ntp + 1][0] = t0[2]; bH[2 * ntp + 1][1] = t0[3];
                if (full) {
                    ldsm_x4(t1, br + MATW);
                    bL[2 * ntp][0] = t1[0]; bL[2 * ntp][1] = t1[1];
                    bL[2 * ntp + 1][0] = t1[2]; bL[2 * ntp + 1][1] = t1[3];
                }
            }
#pragma unroll
            for (int mt = 0; mt < 4; mt++)
#pragma unroll
                for (int nt = 0; nt < 8; nt++) {
                    mma16816(acc[mt][nt], aH[mt], bH[nt]);
                    if (full) {
                        mma16816(acc[mt][nt], aH[mt], bL[nt]);
                        mma16816(acc[mt][nt], aL[mt], bH[nt]);
                    }
                }
        }
        __syncthreads();
    }

    // Epilogue: bias, scale, fp16 hi/lo split, head-major store
    int r = lane >> 2, c2 = (lane & 3) * 2;
#pragma unroll
    for (int mt = 0; mt < 4; mt++) {
#pragma unroll
        for (int nt = 0; nt < 8; nt++) {
            int col = bn + wn * 64 + nt * 8 + c2;
            float2 bb = *(const float2*)(bias + col);
            int hh = col >> 6, dd = col & 63;
#pragma unroll
            for (int half = 0; half < 2; half++) {
                int row = bm + wm * 64 + mt * 16 + r + half * 8;
                int bb_i = row >> 10, ll = row & 1023;
                size_t dst = ((size_t)((bb_i * Hn + hh) * Ln + ll)) * 64 + dd;
                float v0 = (acc[mt][nt][2 * half + 0] + bb.x) * scale;
                float v1 = (acc[mt][nt][2 * half + 1] + bb.y) * scale;
                __half2 h2v = __floats2half2_rn(v0, v1);
                *(__half2*)(Ohi + dst) = h2v;
                if (full) {
                    float2 hf = __half22float2(h2v);
                    __half2 l2v = __floats2half2_rn(v0 - hf.x, v1 - hf.y);
                    *(__half2*)(Olo + dst) = l2v;
                }
            }
        }
    }
}

// ---------------------------------------------------------------------------
// Tensor-core causal flash attention.
// S = QK^T: fp16 split-3. O += PV: single fp16 MMA (P_hi x V_hi).
// CTA: 128 q-rows per (b,h); EIGHT warps x 16 rows (4 warps/SMSP at 2 CTAs/SM
// — latency hiding for the serial softmax chain); K tiles of 64
// double-buffered (Khi, Klo, Vhi); ex2.approx softmax; qt descending.
// ---------------------------------------------------------------------------
#define ROWB 144                       // 72 fp16 per row
#define MATB (64 * ROWB)               // 9216
#define STG  (3 * MATB)                // 27648 (Khi, Klo, Vhi)
#define KMOFF (2 * STG)                // 55296: kmask staging (2 x 256B)
#define QOFF_H (KMOFF + 512)           // 55808
#define QOFF_L (QOFF_H + 128 * ROWB)   // 74240
#define ATTN_SMEM (QOFF_L + 128 * ROWB)   // 92672

__global__ void __launch_bounds__(256, 2) attn_mma(const float* __restrict__ queries,
                                                   float* __restrict__ out) {
    extern __shared__ char smraw[];
    uint32_t sb = smem_u32(smraw);
    int tid = threadIdx.x, wid = tid >> 5, lane = tid & 31;
    int qt = (int)gridDim.x - 1 - (int)blockIdx.x;   // heavy tiles first
    int h = blockIdx.y, b = blockIdx.z;
    int bh = b * Hn + h;
    int wq0 = wid * 16;                // 8 warps x 16 rows

    const __half* Qh = g_prjh[0] + (size_t)bh * Ln * 64;
    const __half* Ql = g_prjl[0] + (size_t)bh * Ln * 64;
    const __half* Kh = g_prjh[1] + (size_t)bh * Ln * 64;
    const __half* Kl = g_prjl[1] + (size_t)bh * Ln * 64;
    const __half* Vh = g_prjh[2] + (size_t)bh * Ln * 64;

    // ---- Q tile into dedicated SMEM ----
#pragma unroll
    for (int i = 0; i < 4; i++) {
        int idx = tid + 256 * i;          // 0..1023
        int row = idx >> 3, ch = idx & 7;
        cp16(sb + QOFF_H + row * ROWB + ch * 16,
             Qh + (size_t)(qt * 128 + row) * 64 + ch * 8);
        cp16(sb + QOFF_L + row * ROWB + ch * 16,
             Ql + (size_t)(qt * 128 + row) * 64 + ch * 8);
    }
    CP_COMMIT();

    float o[8][4];
#pragma unroll
    for (int nt = 0; nt < 8; nt++)
#pragma unroll
        for (int e = 0; e < 4; e++) o[nt][e] = 0.f;
    float mrow0 = -INFINITY, mrow1 = -INFINITY, lsum0 = 0.f, lsum1 = 0.f;

    int ntk = 2 * qt + 2;

    auto load_kv = [&](int kt2) {
        uint32_t st = sb + (uint32_t)(kt2 & 1) * STG;
        int kg0 = kt2 * 64;
        const __half* srcs[3] = {Kh, Kl, Vh};
#pragma unroll
        for (int m = 0; m < 3; m++) {
#pragma unroll
            for (int i = 0; i < 2; i++) {
                int idx = tid + 256 * i;   // 0..511
                int row = idx >> 3, ch = idx & 7;
                cp16(st + m * MATB + row * ROWB + ch * 16,
                     srcs[m] + (size_t)(kg0 + row) * 64 + ch * 8);
            }
        }
        if (tid < 16)
            cp16(sb + KMOFF + (uint32_t)(kt2 & 1) * 256 + tid * 16,
                 g_kmask + b * Ln + kg0 + tid * 4);
        CP_COMMIT();
    };

    load_kv(0);

    int c2 = (lane & 3) * 2, rr = lane >> 2;
    int row0 = qt * 128 + wq0 + rr, row1 = row0 + 8;

#pragma unroll 1
    for (int kt = 0; kt < ntk; kt++) {
        if (kt + 1 < ntk) {
            load_kv(kt + 1);
            asm volatile("cp.async.wait_group 1;\n" ::: "memory");
        } else {
            asm volatile("cp.async.wait_group 0;\n" ::: "memory");
        }
        __syncthreads();
        uint32_t st = sb + (uint32_t)(kt & 1) * STG;

        // ---- S = Q K^T  (fp16 split-3; base-2 domain) ----
        float s[8][4];
#pragma unroll
        for (int nt = 0; nt < 8; nt++)
#pragma unroll
            for (int e = 0; e < 4; e++) s[nt][e] = 0.f;

#pragma unroll
        for (int dk = 0; dk < 4; dk++) {
            uint32_t qfh[4], qfl[4];
            uint32_t ar = sb + QOFF_H
                + (uint32_t)((wq0 + (lane & 15)) * ROWB)
                + (uint32_t)((dk * 16 + (lane >> 4) * 8) * 2);
            ldsm_x4(qfh, ar);
            ldsm_x4(qfl, ar + (QOFF_L - QOFF_H));
#pragma unroll
            for (int ntp = 0; ntp < 4; ntp++) {
                uint32_t br = st
                    + (uint32_t)((ntp * 16 + (lane & 7) + ((lane >> 4) & 1) * 8) * ROWB)
                    + (uint32_t)((dk * 16 + ((lane >> 3) & 1) * 8) * 2);
                uint32_t th[4], tl[4];
                ldsm_x4(th, br);
                ldsm_x4(tl, br + MATB);
                mma16816(s[2 * ntp],     qfh, &th[0]);
                mma16816(s[2 * ntp],     qfh, &tl[0]);
                mma16816(s[2 * ntp],     qfl, &th[0]);
                mma16816(s[2 * ntp + 1], qfh, &th[2]);
                mma16816(s[2 * ntp + 1], qfh, &tl[2]);
                mma16816(s[2 * ntp + 1], qfl, &th[2]);
            }
        }

        // ---- masks ----
        const float* kmp = (const float*)(smraw + KMOFF + (kt & 1) * 256);
        int kbase = kt * 64;
#pragma unroll
        for (int nt = 0; nt < 8; nt++) {
            int col = kbase + nt * 8 + c2;
            float km0 = kmp[nt * 8 + c2];
            float km1 = kmp[nt * 8 + c2 + 1];
            if (km0 == 0.f || col > row0)     s[nt][0] = NEGC;
            if (km1 == 0.f || col + 1 > row0) s[nt][1] = NEGC;
            if (km0 == 0.f || col > row1)     s[nt][2] = NEGC;
            if (km1 == 0.f || col + 1 > row1) s[nt][3] = NEGC;
        }

        // ---- online softmax (base-2, ex2.approx) ----
        float mx0 = -INFINITY, mx1 = -INFINITY;
#pragma unroll
        for (int nt = 0; nt < 8; nt++) {
            mx0 = fmaxf(mx0, fmaxf(s[nt][0], s[nt][1]));
            mx1 = fmaxf(mx1, fmaxf(s[nt][2], s[nt][3]));
        }
        mx0 = fmaxf(mx0, __shfl_xor_sync(0xffffffffu, mx0, 1));
        mx0 = fmaxf(mx0, __shfl_xor_sync(0xffffffffu, mx0, 2));
        mx1 = fmaxf(mx1, __shfl_xor_sync(0xffffffffu, mx1, 1));
        mx1 = fmaxf(mx1, __shfl_xor_sync(0xffffffffu, mx1, 2));
        float mn0 = fmaxf(mrow0, mx0), mn1 = fmaxf(mrow1, mx1);
        float corr0 = ex2(mrow0 - mn0), corr1 = ex2(mrow1 - mn1);
        mrow0 = mn0; mrow1 = mn1;

        float ps0 = 0.f, ps1 = 0.f;
#pragma unroll
        for (int nt = 0; nt < 8; nt++) {
            s[nt][0] = ex2(s[nt][0] - mn0);
            s[nt][1] = ex2(s[nt][1] - mn0);
            s[nt][2] = ex2(s[nt][2] - mn1);
            s[nt][3] = ex2(s[nt][3] - mn1);
            ps0 += s[nt][0] + s[nt][1];
            ps1 += s[nt][2] + s[nt][3];
        }
        ps0 += __shfl_xor_sync(0xffffffffu, ps0, 1);
        ps0 += __shfl_xor_sync(0xffffffffu, ps0, 2);
        ps1 += __shfl_xor_sync(0xffffffffu, ps1, 1);
        ps1 += __shfl_xor_sync(0xffffffffu, ps1, 2);
        lsum0 = lsum0 * corr0 + ps0;
        lsum1 = lsum1 * corr1 + ps1;
#pragma unroll
        for (int nt = 0; nt < 8; nt++) {
            o[nt][0] *= corr0; o[nt][1] *= corr0;
            o[nt][2] *= corr1; o[nt][3] *= corr1;
        }

        // ---- O += P V  (single fp16 MMA per tile: P_hi x V_hi) ----
#pragma unroll
        for (int ks = 0; ks < 4; ks++) {
            uint32_t aH[4];
#pragma unroll
            for (int half = 0; half < 2; half++) {
                int nt = 2 * ks + half;
                aH[2 * half + 0] = pack_h2(s[nt][0], s[nt][1]);
                aH[2 * half + 1] = pack_h2(s[nt][2], s[nt][3]);
            }
#pragma unroll
            for (int ntp = 0; ntp < 4; ntp++) {
                uint32_t br = st + 2 * MATB
                    + (uint32_t)((ks * 16 + (lane & 7) + ((lane >> 3) & 1) * 8) * ROWB)
                    + (uint32_t)((ntp * 16 + ((lane >> 4) & 1) * 8) * 2);
                uint32_t vh[4];
                ldsm_x4_t(vh, br);
                mma16816(o[2 * ntp],     aH, &vh[0]);
                mma16816(o[2 * ntp + 1], aH, &vh[2]);
            }
        }
        __syncthreads();
    }

    // ---- epilogue: normalize, query mask, residual, fp32 store ----
    float qm0 = g_qmask[b * Ln + row0];
    float qm1 = g_qmask[b * Ln + row1];
    float f0 = qm0 / lsum0, f1 = qm1 / lsum1;
    size_t base0 = ((size_t)(b * Ln + row0)) * Dn + h * 64;
    size_t base1 = ((size_t)(b * Ln + row1)) * Dn + h * 64;
#pragma unroll
    for (int nt = 0; nt < 8; nt++) {
        int d = nt * 8 + c2;
        float2 r0v = *(const float2*)(queries + base0 + d);
        float2 r1v = *(const float2*)(queries + base1 + d);
        float2 o0, o1;
        o0.x = o[nt][0] * f0 + r0v.x; o0.y = o[nt][1] * f0 + r0v.y;
        o1.x = o[nt][2] * f1 + r1v.x; o1.y = o[nt][3] * f1 + r1v.y;
        *(float2*)(out + base0 + d) = o0;
        *(float2*)(out + base1 + d) = o1;
    }
}

// ---------------------------------------------------------------------------
extern "C" void kernel_launch(void* const* d_in, const int* in_sizes, int n_in,
                              void* d_out, int out_size) {
    (void)in_sizes; (void)n_in; (void)out_size;
    const float* queries = (const float*)d_in[0];
    const float* keys    = (const float*)d_in[1];
    const float* Wq = (const float*)d_in[2];
    const float* bq = (const float*)d_in[3];
    const float* Wk = (const float*)d_in[4];
    const float* bk = (const float*)d_in[5];
    const float* Wv = (const float*)d_in[6];
    const float* bv = (const float*)d_in[7];
    float* out = (float*)d_out;

    cudaFuncSetAttribute(gemm_mma,
                         cudaFuncAttributeMaxDynamicSharedMemorySize, GEMM_SMEM);
    cudaFuncSetAttribute(attn_mma,
                         cudaFuncAttributeMaxDynamicSharedMemorySize, ATTN_SMEM);

    // 1) fused fp16 hi/lo splits + padding masks
    cvt_all<<<8384, 256>>>(queries, keys, Wq, Wk, Wv);

    // 2) QKV projections (tensor cores); V projection single-MMA
    gemm_mma<<<dim3(4, 128, 3), 256, GEMM_SMEM>>>(bq, bk, bv);

    // 3) tensor-core attention + residual (8 warps x 16 rows, 2 CTAs/SM)
    attn_mma<<<dim3(8, 8, 32), 256, ATTN_SMEM>>>(queries, out);
}

// round 13
// speedup vs baseline: 1.1269x; 1.1269x over previous
#include <cuda_runtime.h>
#include <cuda_fp16.h>
#include <math.h>
#include <cstdint>

// Problem dims (fixed by reference)
#define Bn  32
#define Ln  1024
#define Dn  512
#define Hn  8
#define DHn 64

#define NEGC (-4294967295.0f)   // -2^32 + 1, matches reference padding value
#define LOG2E 1.4426950408889634f

// ---------------------------------------------------------------------------
// Scratch (allocation-free rule: static __device__ globals)
// ---------------------------------------------------------------------------
__device__ float g_kmask[Bn * Ln];
__device__ float g_qmask[Bn * Ln];

#define NELEM_A ((size_t)Bn * Ln * Dn)      // 16,777,216
#define NELEM_W ((size_t)Dn * Dn)           // 262,144
__device__ __half g_qhi[NELEM_A];
__device__ __half g_qlo[NELEM_A];
__device__ __half g_khi[NELEM_A];
__device__ __half g_klo[NELEM_A];
__device__ __half g_whi[3][NELEM_W];
__device__ __half g_wlo[3][NELEM_W];

// Projected Q/K/V, fp16, head-major layout [b][h][l][64].
// z: 0 = Q (pre-scaled by log2e/8; hi+lo), 1 = K (hi only), 2 = V (hi only)
__device__ __half g_prjh[3][NELEM_A];
__device__ __half g_prjl[3][NELEM_A];

// ---------------------------------------------------------------------------
// PTX helpers (sm_80-baseline only — tcgen05 does NOT assemble at .target
// sm_103 in this harness)
// ---------------------------------------------------------------------------
__device__ __forceinline__ uint32_t smem_u32(const void* p) {
    uint32_t a;
    asm("{ .reg .u64 t; cvta.to.shared.u64 t, %1; cvt.u32.u64 %0, t; }"
        : "=r"(a) : "l"(p));
    return a;
}
__device__ __forceinline__ void cp16(uint32_t dst, const void* src) {
    asm volatile("cp.async.cg.shared.global [%0], [%1], 16;\n"
                 :: "r"(dst), "l"(src) : "memory");
}
#define CP_COMMIT() asm volatile("cp.async.commit_group;\n" ::: "memory")

__device__ __forceinline__ void ldsm_x4(uint32_t* r, uint32_t addr) {
    asm volatile("ldmatrix.sync.aligned.m8n8.x4.shared.b16 {%0,%1,%2,%3}, [%4];"
                 : "=r"(r[0]), "=r"(r[1]), "=r"(r[2]), "=r"(r[3]) : "r"(addr));
}
__device__ __forceinline__ void ldsm_x4_t(uint32_t* r, uint32_t addr) {
    asm volatile("ldmatrix.sync.aligned.m8n8.x4.trans.shared.b16 {%0,%1,%2,%3}, [%4];"
                 : "=r"(r[0]), "=r"(r[1]), "=r"(r[2]), "=r"(r[3]) : "r"(addr));
}
__device__ __forceinline__ void mma16816(float* d, const uint32_t* a, const uint32_t* b) {
    asm volatile(
        "mma.sync.aligned.m16n8k16.row.col.f32.f16.f16.f32 "
        "{%0,%1,%2,%3}, {%4,%5,%6,%7}, {%8,%9}, {%0,%1,%2,%3};"
        : "+f"(d[0]), "+f"(d[1]), "+f"(d[2]), "+f"(d[3])
        : "r"(a[0]), "r"(a[1]), "r"(a[2]), "r"(a[3]), "r"(b[0]), "r"(b[1]));
}
__device__ __forceinline__ uint32_t pack_h2(float a, float b) {
    __half2 t = __floats2half2_rn(a, b);
    return *(uint32_t*)&t;
}
__device__ __forceinline__ float ex2(float x) {
    float y;
    asm("ex2.approx.f32 %0, %1;" : "=f"(y) : "f"(x));
    return y;
}

// ---------------------------------------------------------------------------
// Fused conversion + padding masks. One warp per 512-elem row.
// ---------------------------------------------------------------------------
__global__ void __launch_bounds__(256) cvt_all(const float* __restrict__ q,
                                               const float* __restrict__ k,
                                               const float* __restrict__ Wq,
                                               const float* __restrict__ Wk,
                                               const float* __restrict__ Wv) {
    int w = blockIdx.x * 8 + (threadIdx.x >> 5);
    int lane = threadIdx.x & 31;
    const float* src;
    __half *hi, *lo;
    float* maskp = nullptr;
    if (w < 65536) {
        int row = w & 32767;
        size_t off = (size_t)row * Dn;
        if (w < 32768) {
            src = q + off; hi = g_qhi + off; lo = g_qlo + off;
            maskp = g_qmask + row;
        } else {
            src = k + off; hi = g_khi + off; lo = g_klo + off;
            maskp = g_kmask + row;
        }
    } else {
        int r = w - 65536;
        int z = r >> 9, row = r & 511;
        size_t off = (size_t)row * Dn;
        src = (z == 0 ? Wq : (z == 1 ? Wk : Wv)) + off;
        hi = g_whi[z] + off; lo = g_wlo[z] + off;
    }
    float s = 0.f;
#pragma unroll
    for (int i = 0; i < 4; i++) {
        int f = lane + 32 * i;
        float4 v = ((const float4*)src)[f];
        s += (v.x + v.y) + (v.z + v.w);
        __half2 h0 = __floats2half2_rn(v.x, v.y);
        __half2 h1 = __floats2half2_rn(v.z, v.w);
        float2 f0 = __half22float2(h0);
        float2 f1 = __half22float2(h1);
        __half2 l0 = __floats2half2_rn(v.x - f0.x, v.y - f0.y);
        __half2 l1 = __floats2half2_rn(v.z - f1.x, v.w - f1.y);
        ((__half2*)hi)[2 * f + 0] = h0;
        ((__half2*)hi)[2 * f + 1] = h1;
        ((__half2*)lo)[2 * f + 0] = l0;
        ((__half2*)lo)[2 * f + 1] = l1;
    }
    if (maskp) {
#pragma unroll
        for (int o = 16; o; o >>= 1) s += __shfl_xor_sync(0xffffffffu, s, o);
        if (lane == 0) *maskp = (s != 0.0f) ? 1.0f : 0.0f;
    }
}

// ---------------------------------------------------------------------------
// fp16-split GEMM (mma.sync): proj_z = A_z @ W_z^T + bias_z -> fp16,
// head-major [b][h][l][64]; Q pre-scaled by log2e/8.
// z = 0 (Q): split-3 MMAs, hi+lo outputs.
// z = 1 (K), 2 (V): SINGLE MMA (A_hi x W_hi), hi-only output — consumers
// (S and PV) only read the hi parts, so extra precision is wasted.
// CTA tile 256x128, 8 warps, warp tile 64x64, K chunks of 32, 2-stage cp.async.
// ---------------------------------------------------------------------------
#define MATA   20480                 // 256 rows * 80B
#define MATW   10240                 // 128 rows * 80B
#define STAGE_B (2 * MATA + 2 * MATW)  // 61440
#define GEMM_SMEM (2 * STAGE_B)        // 122880

__device__ __forceinline__ void load_stage(uint32_t st,
                                           const __half* Ahi,
                                           const __half* Alo,
                                           const __half* Whi,
                                           const __half* Wlo,
                                           int bm, int bn, int kc, int tid,
                                           bool full) {
#pragma unroll
    for (int i = 0; i < 4; i++) {
        int idx = tid + 256 * i;            // 0..1023
        int row = idx >> 2, q4 = idx & 3;
        cp16(st + row * 80 + q4 * 16,
             Ahi + (size_t)(bm + row) * Dn + kc * 32 + q4 * 8);
    }
#pragma unroll
    for (int i = 0; i < 2; i++) {
        int idx = tid + 256 * i;            // 0..511
        int row = idx >> 2, q4 = idx & 3;
        cp16(st + 2 * MATA + row * 80 + q4 * 16,
             Whi + (size_t)(bn + row) * Dn + kc * 32 + q4 * 8);
    }
    if (full) {
#pragma unroll
        for (int i = 0; i < 4; i++) {
            int idx = tid + 256 * i;
            int row = idx >> 2, q4 = idx & 3;
            cp16(st + MATA + row * 80 + q4 * 16,
                 Alo + (size_t)(bm + row) * Dn + kc * 32 + q4 * 8);
        }
#pragma unroll
        for (int i = 0; i < 2; i++) {
            int idx = tid + 256 * i;
            int row = idx >> 2, q4 = idx & 3;
            cp16(st + 2 * MATA + MATW + row * 80 + q4 * 16,
                 Wlo + (size_t)(bn + row) * Dn + kc * 32 + q4 * 8);
        }
    }
    CP_COMMIT();
}

__global__ void __launch_bounds__(256, 1) gemm_mma(const float* __restrict__ bq,
                                                   const float* __restrict__ bk,
                                                   const float* __restrict__ bv) {
    extern __shared__ char smem_raw[];
    uint32_t sbase = smem_u32(smem_raw);
    int tid = threadIdx.x;
    int wid = tid >> 5, lane = tid & 31;
    int wm = wid & 3;
    int wn = wid >> 2;
    int z = blockIdx.z;
    int bn = blockIdx.x * 128;
    int bm = blockIdx.y * 256;
    bool full = (z == 0);             // K and V: single-MMA path

    const __half* Ahi = (z == 0) ? g_qhi : g_khi;
    const __half* Alo = (z == 0) ? g_qlo : g_klo;
    const __half* Whi = g_whi[z];
    const __half* Wlo = g_wlo[z];
    const float* bias = (z == 0) ? bq : (z == 1 ? bk : bv);
    float scale = (z == 0) ? (0.125f * LOG2E) : 1.0f;
    __half* Ohi = g_prjh[z];
    __half* Olo = g_prjl[z];

    float acc[4][8][4];
#pragma unroll
    for (int mt = 0; mt < 4; mt++)
#pragma unroll
        for (int nt = 0; nt < 8; nt++)
#pragma unroll
            for (int e = 0; e < 4; e++) acc[mt][nt][e] = 0.f;

    int a_row = lane & 15;
    int a_koff = (lane >> 4) * 16;
    int g = lane >> 3;
    int b_nadd = ((g >> 1) & 1) * 8 + (lane & 7);
    int b_kadd = (g & 1) * 8;

    load_stage(sbase, Ahi, Alo, Whi, Wlo, bm, bn, 0, tid, full);

#pragma unroll 1
    for (int s = 0; s < 16; s++) {
        if (s < 15) {
            load_stage(sbase + (uint32_t)((s + 1) & 1) * STAGE_B,
                       Ahi, Alo, Whi, Wlo, bm, bn, s + 1, tid, full);
            asm volatile("cp.async.wait_group 1;\n" ::: "memory");
        } else {
            asm volatile("cp.async.wait_group 0;\n" ::: "memory");
        }
        __syncthreads();
        uint32_t st = sbase + (uint32_t)(s & 1) * STAGE_B;

#pragma unroll
        for (int ks = 0; ks < 32; ks += 16) {
            uint32_t aH[4][4], aL[4][4], bH[8][2], bL[8][2];
#pragma unroll
            for (int mt = 0; mt < 4; mt++) {
                uint32_t ar = st + (uint32_t)((wm * 64 + mt * 16 + a_row) * 80)
                            + a_koff + ks * 2;
                ldsm_x4(aH[mt], ar);
                if (full) ldsm_x4(aL[mt], ar + MATA);
            }
#pragma unroll
            for (int ntp = 0; ntp < 4; ntp++) {
                uint32_t br = st + 2 * MATA
                            + (uint32_t)((wn * 64 + ntp * 16 + b_nadd) * 80)
                            + (ks + b_kadd) * 2;
                uint32_t t0[4], t1[4];
                ldsm_x4(t0, br);
                bH[2 * ntp][0] = t0[0]; bH[2 * ntp][1] = t0[1];
                bH[2 * ntp + 1][0] = t0[2]; bH[2 * ntp + 1][1] = t0[3];
                if (full) {
                    ldsm_x4(t1, br + MATW);
                    bL[2 * ntp][0] = t1[0]; bL[2 * ntp][1] = t1[1];
                    bL[2 * ntp + 1][0] = t1[2]; bL[2 * ntp + 1][1] = t1[3];
                }
            }
#pragma unroll
            for (int mt = 0; mt < 4; mt++)
#pragma unroll
                for (int nt = 0; nt < 8; nt++) {
                    mma16816(acc[mt][nt], aH[mt], bH[nt]);
                    if (full) {
                        mma16816(acc[mt][nt], aH[mt], bL[nt]);
                        mma16816(acc[mt][nt], aL[mt], bH[nt]);
                    }
                }
        }
        __syncthreads();
    }

    // Epilogue: bias, scale, fp16 split, head-major store
    int r = lane >> 2, c2 = (lane & 3) * 2;
#pragma unroll
    for (int mt = 0; mt < 4; mt++) {
#pragma unroll
        for (int nt = 0; nt < 8; nt++) {
            int col = bn + wn * 64 + nt * 8 + c2;
            float2 bb = *(const float2*)(bias + col);
            int hh = col >> 6, dd = col & 63;
#pragma unroll
            for (int half = 0; half < 2; half++) {
                int row = bm + wm * 64 + mt * 16 + r + half * 8;
                int bb_i = row >> 10, ll = row & 1023;
                size_t dst = ((size_t)((bb_i * Hn + hh) * Ln + ll)) * 64 + dd;
                float v0 = (acc[mt][nt][2 * half + 0] + bb.x) * scale;
                float v1 = (acc[mt][nt][2 * half + 1] + bb.y) * scale;
                __half2 h2v = __floats2half2_rn(v0, v1);
                *(__half2*)(Ohi + dst) = h2v;
                if (full) {
                    float2 hf = __half22float2(h2v);
                    __half2 l2v = __floats2half2_rn(v0 - hf.x, v1 - hf.y);
                    *(__half2*)(Olo + dst) = l2v;
                }
            }
        }
    }
}

// ---------------------------------------------------------------------------
// Tensor-core causal flash attention.
// S = QK^T: 2 MMAs (Qhi·Khi + Qlo·Khi — K is hi-only). O += PV: 1 MMA.
// CTA: 128 q-rows per (b,h); 4 warps x 32 rows (R11 config — best measured);
// K tiles of 64 double-buffered (Khi, Vhi only); ex2 softmax; qt descending;
// 2 CTAs/SM.
// ---------------------------------------------------------------------------
#define ROWB 144                       // 72 fp16 per row
#define MATB (64 * ROWB)               // 9216
#define STG  (2 * MATB)                // 18432 (Khi, Vhi)
#define KMOFF (2 * STG)                // 36864: kmask staging (2 x 256B)
#define QOFF_H (KMOFF + 512)           // 37376
#define QOFF_L (QOFF_H + 128 * ROWB)   // 55808
#define ATTN_SMEM (QOFF_L + 128 * ROWB)   // 74240

__global__ void __launch_bounds__(128, 2) attn_mma(const float* __restrict__ queries,
                                                   float* __restrict__ out) {
    extern __shared__ char smraw[];
    uint32_t sb = smem_u32(smraw);
    int tid = threadIdx.x, wid = tid >> 5, lane = tid & 31;
    int qt = (int)gridDim.x - 1 - (int)blockIdx.x;   // heavy tiles first
    int h = blockIdx.y, b = blockIdx.z;
    int bh = b * Hn + h;
    int wq0 = wid * 32;

    const __half* Qh = g_prjh[0] + (size_t)bh * Ln * 64;
    const __half* Ql = g_prjl[0] + (size_t)bh * Ln * 64;
    const __half* Kh = g_prjh[1] + (size_t)bh * Ln * 64;
    const __half* Vh = g_prjh[2] + (size_t)bh * Ln * 64;

    // ---- Q tile into dedicated SMEM ----
#pragma unroll
    for (int i = 0; i < 8; i++) {
        int idx = tid + 128 * i;          // 0..1023
        int row = idx >> 3, ch = idx & 7;
        cp16(sb + QOFF_H + row * ROWB + ch * 16,
             Qh + (size_t)(qt * 128 + row) * 64 + ch * 8);
        cp16(sb + QOFF_L + row * ROWB + ch * 16,
             Ql + (size_t)(qt * 128 + row) * 64 + ch * 8);
    }
    CP_COMMIT();

    float o[2][8][4];
#pragma unroll
    for (int mt = 0; mt < 2; mt++)
#pragma unroll
        for (int nt = 0; nt < 8; nt++)
#pragma unroll
            for (int e = 0; e < 4; e++) o[mt][nt][e] = 0.f;
    float mrow[2][2], lsum[2][2];
#pragma unroll
    for (int mt = 0; mt < 2; mt++) {
        mrow[mt][0] = -INFINITY; mrow[mt][1] = -INFINITY;
        lsum[mt][0] = 0.f;       lsum[mt][1] = 0.f;
    }

    int ntk = 2 * qt + 2;

    auto load_kv = [&](int kt2) {
        uint32_t st = sb + (uint32_t)(kt2 & 1) * STG;
        int kg0 = kt2 * 64;
        const __half* srcs[2] = {Kh, Vh};
#pragma unroll
        for (int m = 0; m < 2; m++) {
#pragma unroll
            for (int i = 0; i < 4; i++) {
                int idx = tid + 128 * i;   // 0..511
                int row = idx >> 3, ch = idx & 7;
                cp16(st + m * MATB + row * ROWB + ch * 16,
                     srcs[m] + (size_t)(kg0 + row) * 64 + ch * 8);
            }
        }
        if (tid < 16)
            cp16(sb + KMOFF + (uint32_t)(kt2 & 1) * 256 + tid * 16,
                 g_kmask + b * Ln + kg0 + tid * 4);
        CP_COMMIT();
    };

    load_kv(0);

    int c2 = (lane & 3) * 2, rr = lane >> 2;
    int rowq[2][2];
#pragma unroll
    for (int mt = 0; mt < 2; mt++) {
        rowq[mt][0] = qt * 128 + wq0 + mt * 16 + rr;
        rowq[mt][1] = rowq[mt][0] + 8;
    }

#pragma unroll 1
    for (int kt = 0; kt < ntk; kt++) {
        if (kt + 1 < ntk) {
            load_kv(kt + 1);
            asm volatile("cp.async.wait_group 1;\n" ::: "memory");
        } else {
            asm volatile("cp.async.wait_group 0;\n" ::: "memory");
        }
        __syncthreads();
        uint32_t st = sb + (uint32_t)(kt & 1) * STG;

        // ---- S = Q K^T  (2 MMAs: Qhi·Khi + Qlo·Khi; base-2 domain) ----
        float s[2][8][4];
#pragma unroll
        for (int mt = 0; mt < 2; mt++)
#pragma unroll
            for (int nt = 0; nt < 8; nt++)
#pragma unroll
                for (int e = 0; e < 4; e++) s[mt][nt][e] = 0.f;

#pragma unroll
        for (int dk = 0; dk < 4; dk++) {
            uint32_t qfh[2][4], qfl[2][4];
#pragma unroll
            for (int mt = 0; mt < 2; mt++) {
                uint32_t ar = sb + QOFF_H
                    + (uint32_t)((wq0 + mt * 16 + (lane & 15)) * ROWB)
                    + (uint32_t)((dk * 16 + (lane >> 4) * 8) * 2);
                ldsm_x4(qfh[mt], ar);
                ldsm_x4(qfl[mt], ar + (QOFF_L - QOFF_H));
            }
#pragma unroll
            for (int ntp = 0; ntp < 4; ntp++) {
                uint32_t br = st
                    + (uint32_t)((ntp * 16 + (lane & 7) + ((lane >> 4) & 1) * 8) * ROWB)
                    + (uint32_t)((dk * 16 + ((lane >> 3) & 1) * 8) * 2);
                uint32_t th[4];
                ldsm_x4(th, br);
#pragma unroll
                for (int mt = 0; mt < 2; mt++) {
                    mma16816(s[mt][2 * ntp],     qfh[mt], &th[0]);
                    mma16816(s[mt][2 * ntp],     qfl[mt], &th[0]);
                    mma16816(s[mt][2 * ntp + 1], qfh[mt], &th[2]);
                    mma16816(s[mt][2 * ntp + 1], qfl[mt], &th[2]);
                }
            }
        }

        // ---- masks ----
        const float* kmp = (const float*)(smraw + KMOFF + (kt & 1) * 256);
        int kbase = kt * 64;
#pragma unroll
        for (int nt = 0; nt < 8; nt++) {
            int col = kbase + nt * 8 + c2;
            float km0 = kmp[nt * 8 + c2];
            float km1 = kmp[nt * 8 + c2 + 1];
#pragma unroll
            for (int mt = 0; mt < 2; mt++) {
                if (km0 == 0.f || col > rowq[mt][0])     s[mt][nt][0] = NEGC;
                if (km1 == 0.f || col + 1 > rowq[mt][0]) s[mt][nt][1] = NEGC;
                if (km0 == 0.f || col > rowq[mt][1])     s[mt][nt][2] = NEGC;
                if (km1 == 0.f || col + 1 > rowq[mt][1]) s[mt][nt][3] = NEGC;
            }
        }

        // ---- online softmax (base-2, ex2.approx) ----
#pragma unroll
        for (int mt = 0; mt < 2; mt++) {
            float mx0 = -INFINITY, mx1 = -INFINITY;
#pragma unroll
            for (int nt = 0; nt < 8; nt++) {
                mx0 = fmaxf(mx0, fmaxf(s[mt][nt][0], s[mt][nt][1]));
                mx1 = fmaxf(mx1, fmaxf(s[mt][nt][2], s[mt][nt][3]));
            }
            mx0 = fmaxf(mx0, __shfl_xor_sync(0xffffffffu, mx0, 1));
            mx0 = fmaxf(mx0, __shfl_xor_sync(0xffffffffu, mx0, 2));
            mx1 = fmaxf(mx1, __shfl_xor_sync(0xffffffffu, mx1, 1));
            mx1 = fmaxf(mx1, __shfl_xor_sync(0xffffffffu, mx1, 2));
            float mn0 = fmaxf(mrow[mt][0], mx0), mn1 = fmaxf(mrow[mt][1], mx1);
            float corr0 = ex2(mrow[mt][0] - mn0), corr1 = ex2(mrow[mt][1] - mn1);
            mrow[mt][0] = mn0; mrow[mt][1] = mn1;

            float ps0 = 0.f, ps1 = 0.f;
#pragma unroll
            for (int nt = 0; nt < 8; nt++) {
                s[mt][nt][0] = ex2(s[mt][nt][0] - mn0);
                s[mt][nt][1] = ex2(s[mt][nt][1] - mn0);
                s[mt][nt][2] = ex2(s[mt][nt][2] - mn1);
                s[mt][nt][3] = ex2(s[mt][nt][3] - mn1);
                ps0 += s[mt][nt][0] + s[mt][nt][1];
                ps1 += s[mt][nt][2] + s[mt][nt][3];
            }
            ps0 += __shfl_xor_sync(0xffffffffu, ps0, 1);
            ps0 += __shfl_xor_sync(0xffffffffu, ps0, 2);
            ps1 += __shfl_xor_sync(0xffffffffu, ps1, 1);
            ps1 += __shfl_xor_sync(0xffffffffu, ps1, 2);
            lsum[mt][0] = lsum[mt][0] * corr0 + ps0;
            lsum[mt][1] = lsum[mt][1] * corr1 + ps1;
#pragma unroll
            for (int nt = 0; nt < 8; nt++) {
                o[mt][nt][0] *= corr0; o[mt][nt][1] *= corr0;
                o[mt][nt][2] *= corr1; o[mt][nt][3] *= corr1;
            }
        }

        // ---- O += P V  (single fp16 MMA per tile: P_hi x V_hi) ----
#pragma unroll
        for (int ks = 0; ks < 4; ks++) {
            uint32_t aH[2][4];
#pragma unroll
            for (int mt = 0; mt < 2; mt++) {
#pragma unroll
                for (int half = 0; half < 2; half++) {
                    int nt = 2 * ks + half;
                    aH[mt][2 * half + 0] = pack_h2(s[mt][nt][0], s[mt][nt][1]);
                    aH[mt][2 * half + 1] = pack_h2(s[mt][nt][2], s[mt][nt][3]);
                }
            }
#pragma unroll
            for (int ntp = 0; ntp < 4; ntp++) {
                uint32_t br = st + MATB
                    + (uint32_t)((ks * 16 + (lane & 7) + ((lane >> 3) & 1) * 8) * ROWB)
                    + (uint32_t)((ntp * 16 + ((lane >> 4) & 1) * 8) * 2);
                uint32_t vh[4];
                ldsm_x4_t(vh, br);
#pragma unroll
                for (int mt = 0; mt < 2; mt++) {
                    mma16816(o[mt][2 * ntp],     aH[mt], &vh[0]);
                    mma16816(o[mt][2 * ntp + 1], aH[mt], &vh[2]);
                }
            }
        }
        __syncthreads();
    }

    // ---- epilogue: normalize, query mask, residual, fp32 store ----
#pragma unroll
    for (int mt = 0; mt < 2; mt++) {
        float qm0 = g_qmask[b * Ln + rowq[mt][0]];
        float qm1 = g_qmask[b * Ln + rowq[mt][1]];
        float f0 = qm0 / lsum[mt][0], f1 = qm1 / lsum[mt][1];
        size_t base0 = ((size_t)(b * Ln + rowq[mt][0])) * Dn + h * 64;
        size_t base1 = ((size_t)(b * Ln + rowq[mt][1])) * Dn + h * 64;
#pragma unroll
        for (int nt = 0; nt < 8; nt++) {
            int d = nt * 8 + c2;
            float2 r0v = *(const float2*)(queries + base0 + d);
            float2 r1v = *(const float2*)(queries + base1 + d);
            float2 o0, o1;
            o0.x = o[mt][nt][0] * f0 + r0v.x; o0.y = o[mt][nt][1] * f0 + r0v.y;
            o1.x = o[mt][nt][2] * f1 + r1v.x; o1.y = o[mt][nt][3] * f1 + r1v.y;
            *(float2*)(out + base0 + d) = o0;
            *(float2*)(out + base1 + d) = o1;
        }
    }
}

// ---------------------------------------------------------------------------
extern "C" void kernel_launch(void* const* d_in, const int* in_sizes, int n_in,
                              void* d_out, int out_size) {
    (void)in_sizes; (void)n_in; (void)out_size;
    const float* queries = (const float*)d_in[0];
    const float* keys    = (const float*)d_in[1];
    const float* Wq = (const float*)d_in[2];
    const float* bq = (const float*)d_in[3];
    const float* Wk = (const float*)d_in[4];
    const float* bk = (const float*)d_in[5];
    const float* Wv = (const float*)d_in[6];
    const float* bv = (const float*)d_in[7];
    float* out = (float*)d_out;

    cudaFuncSetAttribute(gemm_mma,
                         cudaFuncAttributeMaxDynamicSharedMemorySize, GEMM_SMEM);
    cudaFuncSetAttribute(attn_mma,
                         cudaFuncAttributeMaxDynamicSharedMemorySize, ATTN_SMEM);

    // 1) fused fp16 hi/lo splits + padding masks
    cvt_all<<<8384, 256>>>(queries, keys, Wq, Wk, Wv);

    // 2) QKV projections; K and V single-MMA, Q split-3
    gemm_mma<<<dim3(4, 128, 3), 256, GEMM_SMEM>>>(bq, bk, bv);

    // 3) tensor-core attention + residual (S 2-MMA, PV 1-MMA)
    attn_mma<<<dim3(8, 8, 32), 128, ATTN_SMEM>>>(queries, out);
}

// round 14
// speedup vs baseline: 1.7955x; 1.5933x over previous
#include <cuda_runtime.h>
#include <cuda_fp16.h>
#include <math.h>
#include <cstdint>

// Problem dims (fixed by reference)
#define Bn  32
#define Ln  1024
#define Dn  512
#define Hn  8
#define DHn 64

#define NEGC (-4294967295.0f)   // -2^32 + 1, matches reference padding value
#define LOG2E 1.4426950408889634f

// ---------------------------------------------------------------------------
// Scratch (allocation-free rule: static __device__ globals)
// ---------------------------------------------------------------------------
__device__ float g_kmask[Bn * Ln];
__device__ float g_qmask[Bn * Ln];

#define NELEM_A ((size_t)Bn * Ln * Dn)      // 16,777,216
#define NELEM_W ((size_t)Dn * Dn)           // 262,144
__device__ __half g_qcv[NELEM_A];
__device__ __half g_kcv[NELEM_A];
__device__ __half g_wcv[3][NELEM_W];

// Projected Q/K/V, fp16 (hi-only everywhere), head-major [b][h][l][64].
// z: 0 = Q (pre-scaled by log2e/8 for base-2 softmax), 1 = K, 2 = V
__device__ __half g_prj[3][NELEM_A];

// ---------------------------------------------------------------------------
// PTX helpers (sm_80-baseline only — tcgen05 does NOT assemble at .target
// sm_103 in this harness)
// ---------------------------------------------------------------------------
__device__ __forceinline__ uint32_t smem_u32(const void* p) {
    uint32_t a;
    asm("{ .reg .u64 t; cvta.to.shared.u64 t, %1; cvt.u32.u64 %0, t; }"
        : "=r"(a) : "l"(p));
    return a;
}
__device__ __forceinline__ void cp16(uint32_t dst, const void* src) {
    asm volatile("cp.async.cg.shared.global [%0], [%1], 16;\n"
                 :: "r"(dst), "l"(src) : "memory");
}
#define CP_COMMIT() asm volatile("cp.async.commit_group;\n" ::: "memory")

__device__ __forceinline__ void ldsm_x4(uint32_t* r, uint32_t addr) {
    asm volatile("ldmatrix.sync.aligned.m8n8.x4.shared.b16 {%0,%1,%2,%3}, [%4];"
                 : "=r"(r[0]), "=r"(r[1]), "=r"(r[2]), "=r"(r[3]) : "r"(addr));
}
__device__ __forceinline__ void ldsm_x4_t(uint32_t* r, uint32_t addr) {
    asm volatile("ldmatrix.sync.aligned.m8n8.x4.trans.shared.b16 {%0,%1,%2,%3}, [%4];"
                 : "=r"(r[0]), "=r"(r[1]), "=r"(r[2]), "=r"(r[3]) : "r"(addr));
}
__device__ __forceinline__ void mma16816(float* d, const uint32_t* a, const uint32_t* b) {
    asm volatile(
        "mma.sync.aligned.m16n8k16.row.col.f32.f16.f16.f32 "
        "{%0,%1,%2,%3}, {%4,%5,%6,%7}, {%8,%9}, {%0,%1,%2,%3};"
        : "+f"(d[0]), "+f"(d[1]), "+f"(d[2]), "+f"(d[3])
        : "r"(a[0]), "r"(a[1]), "r"(a[2]), "r"(a[3]), "r"(b[0]), "r"(b[1]));
}
__device__ __forceinline__ uint32_t pack_h2(float a, float b) {
    __half2 t = __floats2half2_rn(a, b);
    return *(uint32_t*)&t;
}
__device__ __forceinline__ float ex2(float x) {
    float y;
    asm("ex2.approx.f32 %0, %1;" : "=f"(y) : "f"(x));
    return y;
}

// ---------------------------------------------------------------------------
// Fused conversion (fp32 -> fp16) + padding masks. One warp per 512-elem row.
// ---------------------------------------------------------------------------
__global__ void __launch_bounds__(256) cvt_all(const float* __restrict__ q,
                                               const float* __restrict__ k,
                                               const float* __restrict__ Wq,
                                               const float* __restrict__ Wk,
                                               const float* __restrict__ Wv) {
    int w = blockIdx.x * 8 + (threadIdx.x >> 5);
    int lane = threadIdx.x & 31;
    const float* src;
    __half* dst;
    float* maskp = nullptr;
    if (w < 65536) {
        int row = w & 32767;
        size_t off = (size_t)row * Dn;
        if (w < 32768) {
            src = q + off; dst = g_qcv + off; maskp = g_qmask + row;
        } else {
            src = k + off; dst = g_kcv + off; maskp = g_kmask + row;
        }
    } else {
        int r = w - 65536;
        int z = r >> 9, row = r & 511;
        size_t off = (size_t)row * Dn;
        src = (z == 0 ? Wq : (z == 1 ? Wk : Wv)) + off;
        dst = g_wcv[z] + off;
    }
    float s = 0.f;
#pragma unroll
    for (int i = 0; i < 4; i++) {
        int f = lane + 32 * i;
        float4 v = ((const float4*)src)[f];
        s += (v.x + v.y) + (v.z + v.w);
        ((__half2*)dst)[2 * f + 0] = __floats2half2_rn(v.x, v.y);
        ((__half2*)dst)[2 * f + 1] = __floats2half2_rn(v.z, v.w);
    }
    if (maskp) {
#pragma unroll
        for (int o = 16; o; o >>= 1) s += __shfl_xor_sync(0xffffffffu, s, o);
        if (lane == 0) *maskp = (s != 0.0f) ? 1.0f : 0.0f;
    }
}

// ---------------------------------------------------------------------------
// fp16 GEMM (mma.sync, single-MMA): proj_z = A_z @ W_z^T + bias_z -> fp16,
// head-major [b][h][l][64]; Q pre-scaled by log2e/8.
// CTA tile 256x128, 8 warps, warp tile 64x64, K chunks of 32, 2-stage cp.async.
// ---------------------------------------------------------------------------
#define MATA   20480                 // 256 rows * 80B
#define MATW   10240                 // 128 rows * 80B
#define STAGE_B (MATA + MATW)          // 30720
#define GEMM_SMEM (2 * STAGE_B)        // 61440

__device__ __forceinline__ void load_stage(uint32_t st,
                                           const __half* A, const __half* W,
                                           int bm, int bn, int kc, int tid) {
#pragma unroll
    for (int i = 0; i < 4; i++) {
        int idx = tid + 256 * i;            // 0..1023
        int row = idx >> 2, q4 = idx & 3;
        cp16(st + row * 80 + q4 * 16,
             A + (size_t)(bm + row) * Dn + kc * 32 + q4 * 8);
    }
#pragma unroll
    for (int i = 0; i < 2; i++) {
        int idx = tid + 256 * i;            // 0..511
        int row = idx >> 2, q4 = idx & 3;
        cp16(st + MATA + row * 80 + q4 * 16,
             W + (size_t)(bn + row) * Dn + kc * 32 + q4 * 8);
    }
    CP_COMMIT();
}

__global__ void __launch_bounds__(256, 1) gemm_mma(const float* __restrict__ bq,
                                                   const float* __restrict__ bk,
                                                   const float* __restrict__ bv) {
    extern __shared__ char smem_raw[];
    uint32_t sbase = smem_u32(smem_raw);
    int tid = threadIdx.x;
    int wid = tid >> 5, lane = tid & 31;
    int wm = wid & 3;
    int wn = wid >> 2;
    int z = blockIdx.z;
    int bn = blockIdx.x * 128;
    int bm = blockIdx.y * 256;

    const __half* A = (z == 0) ? g_qcv : g_kcv;
    const __half* W = g_wcv[z];
    const float* bias = (z == 0) ? bq : (z == 1 ? bk : bv);
    float scale = (z == 0) ? (0.125f * LOG2E) : 1.0f;
    __half* O = g_prj[z];

    float acc[4][8][4];
#pragma unroll
    for (int mt = 0; mt < 4; mt++)
#pragma unroll
        for (int nt = 0; nt < 8; nt++)
#pragma unroll
            for (int e = 0; e < 4; e++) acc[mt][nt][e] = 0.f;

    int a_row = lane & 15;
    int a_koff = (lane >> 4) * 16;
    int g = lane >> 3;
    int b_nadd = ((g >> 1) & 1) * 8 + (lane & 7);
    int b_kadd = (g & 1) * 8;

    load_stage(sbase, A, W, bm, bn, 0, tid);

#pragma unroll 1
    for (int s = 0; s < 16; s++) {
        if (s < 15) {
            load_stage(sbase + (uint32_t)((s + 1) & 1) * STAGE_B,
                       A, W, bm, bn, s + 1, tid);
            asm volatile("cp.async.wait_group 1;\n" ::: "memory");
        } else {
            asm volatile("cp.async.wait_group 0;\n" ::: "memory");
        }
        __syncthreads();
        uint32_t st = sbase + (uint32_t)(s & 1) * STAGE_B;

#pragma unroll
        for (int ks = 0; ks < 32; ks += 16) {
            uint32_t aF[4][4], bF[8][2];
#pragma unroll
            for (int mt = 0; mt < 4; mt++) {
                uint32_t ar = st + (uint32_t)((wm * 64 + mt * 16 + a_row) * 80)
                            + a_koff + ks * 2;
                ldsm_x4(aF[mt], ar);
            }
#pragma unroll
            for (int ntp = 0; ntp < 4; ntp++) {
                uint32_t br = st + MATA
                            + (uint32_t)((wn * 64 + ntp * 16 + b_nadd) * 80)
                            + (ks + b_kadd) * 2;
                uint32_t t0[4];
                ldsm_x4(t0, br);
                bF[2 * ntp][0] = t0[0]; bF[2 * ntp][1] = t0[1];
                bF[2 * ntp + 1][0] = t0[2]; bF[2 * ntp + 1][1] = t0[3];
            }
#pragma unroll
            for (int mt = 0; mt < 4; mt++)
#pragma unroll
                for (int nt = 0; nt < 8; nt++)
                    mma16816(acc[mt][nt], aF[mt], bF[nt]);
        }
        __syncthreads();
    }

    // Epilogue: bias, scale, fp16 store (head-major)
    int r = lane >> 2, c2 = (lane & 3) * 2;
#pragma unroll
    for (int mt = 0; mt < 4; mt++) {
#pragma unroll
        for (int nt = 0; nt < 8; nt++) {
            int col = bn + wn * 64 + nt * 8 + c2;
            float2 bb = *(const float2*)(bias + col);
            int hh = col >> 6, dd = col & 63;
#pragma unroll
            for (int half = 0; half < 2; half++) {
                int row = bm + wm * 64 + mt * 16 + r + half * 8;
                int bb_i = row >> 10, ll = row & 1023;
                size_t dst = ((size_t)((bb_i * Hn + hh) * Ln + ll)) * 64 + dd;
                float v0 = (acc[mt][nt][2 * half + 0] + bb.x) * scale;
                float v1 = (acc[mt][nt][2 * half + 1] + bb.y) * scale;
                *(__half2*)(O + dst) = __floats2half2_rn(v0, v1);
            }
        }
    }
}

// ---------------------------------------------------------------------------
// Tensor-core causal flash attention — pure fp16 (single MMA per matmul).
// S = Q K^T: 1 MMA. O += PV: 1 MMA. CTA: 128 q-rows per (b,h); 4 warps x 32
// rows; K tiles of 64 double-buffered (K, V); ex2 softmax; qt descending;
// 2 CTAs/SM.
// ---------------------------------------------------------------------------
#define ROWB 144                       // 72 fp16 per row
#define MATB (64 * ROWB)               // 9216
#define STG  (2 * MATB)                // 18432 (K, V)
#define KMOFF (2 * STG)                // 36864: kmask staging (2 x 256B)
#define QOFF (KMOFF + 512)             // 37376
#define ATTN_SMEM (QOFF + 128 * ROWB)  // 55808

__global__ void __launch_bounds__(128, 2) attn_mma(const float* __restrict__ queries,
                                                   float* __restrict__ out) {
    extern __shared__ char smraw[];
    uint32_t sb = smem_u32(smraw);
    int tid = threadIdx.x, wid = tid >> 5, lane = tid & 31;
    int qt = (int)gridDim.x - 1 - (int)blockIdx.x;   // heavy tiles first
    int h = blockIdx.y, b = blockIdx.z;
    int bh = b * Hn + h;
    int wq0 = wid * 32;

    const __half* Qp = g_prj[0] + (size_t)bh * Ln * 64;
    const __half* Kp = g_prj[1] + (size_t)bh * Ln * 64;
    const __half* Vp = g_prj[2] + (size_t)bh * Ln * 64;

    // ---- Q tile into dedicated SMEM ----
#pragma unroll
    for (int i = 0; i < 8; i++) {
        int idx = tid + 128 * i;          // 0..1023
        int row = idx >> 3, ch = idx & 7;
        cp16(sb + QOFF + row * ROWB + ch * 16,
             Qp + (size_t)(qt * 128 + row) * 64 + ch * 8);
    }
    CP_COMMIT();

    float o[2][8][4];
#pragma unroll
    for (int mt = 0; mt < 2; mt++)
#pragma unroll
        for (int nt = 0; nt < 8; nt++)
#pragma unroll
            for (int e = 0; e < 4; e++) o[mt][nt][e] = 0.f;
    float mrow[2][2], lsum[2][2];
#pragma unroll
    for (int mt = 0; mt < 2; mt++) {
        mrow[mt][0] = -INFINITY; mrow[mt][1] = -INFINITY;
        lsum[mt][0] = 0.f;       lsum[mt][1] = 0.f;
    }

    int ntk = 2 * qt + 2;

    auto load_kv = [&](int kt2) {
        uint32_t st = sb + (uint32_t)(kt2 & 1) * STG;
        int kg0 = kt2 * 64;
        const __half* srcs[2] = {Kp, Vp};
#pragma unroll
        for (int m = 0; m < 2; m++) {
#pragma unroll
            for (int i = 0; i < 4; i++) {
                int idx = tid + 128 * i;   // 0..511
                int row = idx >> 3, ch = idx & 7;
                cp16(st + m * MATB + row * ROWB + ch * 16,
                     srcs[m] + (size_t)(kg0 + row) * 64 + ch * 8);
            }
        }
        if (tid < 16)
            cp16(sb + KMOFF + (uint32_t)(kt2 & 1) * 256 + tid * 16,
                 g_kmask + b * Ln + kg0 + tid * 4);
        CP_COMMIT();
    };

    load_kv(0);

    int c2 = (lane & 3) * 2, rr = lane >> 2;
    int rowq[2][2];
#pragma unroll
    for (int mt = 0; mt < 2; mt++) {
        rowq[mt][0] = qt * 128 + wq0 + mt * 16 + rr;
        rowq[mt][1] = rowq[mt][0] + 8;
    }

#pragma unroll 1
    for (int kt = 0; kt < ntk; kt++) {
        if (kt + 1 < ntk) {
            load_kv(kt + 1);
            asm volatile("cp.async.wait_group 1;\n" ::: "memory");
        } else {
            asm volatile("cp.async.wait_group 0;\n" ::: "memory");
        }
        __syncthreads();
        uint32_t st = sb + (uint32_t)(kt & 1) * STG;

        // ---- S = Q K^T  (1 MMA per fragment pair; base-2 domain) ----
        float s[2][8][4];
#pragma unroll
        for (int mt = 0; mt < 2; mt++)
#pragma unroll
            for (int nt = 0; nt < 8; nt++)
#pragma unroll
                for (int e = 0; e < 4; e++) s[mt][nt][e] = 0.f;

#pragma unroll
        for (int dk = 0; dk < 4; dk++) {
            uint32_t qf[2][4];
#pragma unroll
            for (int mt = 0; mt < 2; mt++) {
                uint32_t ar = sb + QOFF
                    + (uint32_t)((wq0 + mt * 16 + (lane & 15)) * ROWB)
                    + (uint32_t)((dk * 16 + (lane >> 4) * 8) * 2);
                ldsm_x4(qf[mt], ar);
            }
#pragma unroll
            for (int ntp = 0; ntp < 4; ntp++) {
                uint32_t br = st
                    + (uint32_t)((ntp * 16 + (lane & 7) + ((lane >> 4) & 1) * 8) * ROWB)
                    + (uint32_t)((dk * 16 + ((lane >> 3) & 1) * 8) * 2);
                uint32_t th[4];
                ldsm_x4(th, br);
#pragma unroll
                for (int mt = 0; mt < 2; mt++) {
                    mma16816(s[mt][2 * ntp],     qf[mt], &th[0]);
                    mma16816(s[mt][2 * ntp + 1], qf[mt], &th[2]);
                }
            }
        }

        // ---- masks ----
        const float* kmp = (const float*)(smraw + KMOFF + (kt & 1) * 256);
        int kbase = kt * 64;
#pragma unroll
        for (int nt = 0; nt < 8; nt++) {
            int col = kbase + nt * 8 + c2;
            float km0 = kmp[nt * 8 + c2];
            float km1 = kmp[nt * 8 + c2 + 1];
#pragma unroll
            for (int mt = 0; mt < 2; mt++) {
                if (km0 == 0.f || col > rowq[mt][0])     s[mt][nt][0] = NEGC;
                if (km1 == 0.f || col + 1 > rowq[mt][0]) s[mt][nt][1] = NEGC;
                if (km0 == 0.f || col > rowq[mt][1])     s[mt][nt][2] = NEGC;
                if (km1 == 0.f || col + 1 > rowq[mt][1]) s[mt][nt][3] = NEGC;
            }
        }

        // ---- online softmax (base-2, ex2.approx) ----
#pragma unroll
        for (int mt = 0; mt < 2; mt++) {
            float mx0 = -INFINITY, mx1 = -INFINITY;
#pragma unroll
            for (int nt = 0; nt < 8; nt++) {
                mx0 = fmaxf(mx0, fmaxf(s[mt][nt][0], s[mt][nt][1]));
                mx1 = fmaxf(mx1, fmaxf(s[mt][nt][2], s[mt][nt][3]));
            }
            mx0 = fmaxf(mx0, __shfl_xor_sync(0xffffffffu, mx0, 1));
            mx0 = fmaxf(mx0, __shfl_xor_sync(0xffffffffu, mx0, 2));
            mx1 = fmaxf(mx1, __shfl_xor_sync(0xffffffffu, mx1, 1));
            mx1 = fmaxf(mx1, __shfl_xor_sync(0xffffffffu, mx1, 2));
            float mn0 = fmaxf(mrow[mt][0], mx0), mn1 = fmaxf(mrow[mt][1], mx1);
            float corr0 = ex2(mrow[mt][0] - mn0), corr1 = ex2(mrow[mt][1] - mn1);
            mrow[mt][0] = mn0; mrow[mt][1] = mn1;

            float ps0 = 0.f, ps1 = 0.f;
#pragma unroll
            for (int nt = 0; nt < 8; nt++) {
                s[mt][nt][0] = ex2(s[mt][nt][0] - mn0);
                s[mt][nt][1] = ex2(s[mt][nt][1] - mn0);
                s[mt][nt][2] = ex2(s[mt][nt][2] - mn1);
                s[mt][nt][3] = ex2(s[mt][nt][3] - mn1);
                ps0 += s[mt][nt][0] + s[mt][nt][1];
                ps1 += s[mt][nt][2] + s[mt][nt][3];
            }
            ps0 += __shfl_xor_sync(0xffffffffu, ps0, 1);
            ps0 += __shfl_xor_sync(0xffffffffu, ps0, 2);
            ps1 += __shfl_xor_sync(0xffffffffu, ps1, 1);
            ps1 += __shfl_xor_sync(0xffffffffu, ps1, 2);
            lsum[mt][0] = lsum[mt][0] * corr0 + ps0;
            lsum[mt][1] = lsum[mt][1] * corr1 + ps1;
#pragma unroll
            for (int nt = 0; nt < 8; nt++) {
                o[mt][nt][0] *= corr0; o[mt][nt][1] *= corr0;
                o[mt][nt][2] *= corr1; o[mt][nt][3] *= corr1;
            }
        }

        // ---- O += P V  (1 MMA per fragment pair) ----
#pragma unroll
        for (int ks = 0; ks < 4; ks++) {
            uint32_t aH[2][4];
#pragma unroll
            for (int mt = 0; mt < 2; mt++) {
#pragma unroll
                for (int half = 0; half < 2; half++) {
                    int nt = 2 * ks + half;
                    aH[mt][2 * half + 0] = pack_h2(s[mt][nt][0], s[mt][nt][1]);
                    aH[mt][2 * half + 1] = pack_h2(s[mt][nt][2], s[mt][nt][3]);
                }
            }
#pragma unroll
            for (int ntp = 0; ntp < 4; ntp++) {
                uint32_t br = st + MATB
                    + (uint32_t)((ks * 16 + (lane & 7) + ((lane >> 3) & 1) * 8) * ROWB)
                    + (uint32_t)((ntp * 16 + ((lane >> 4) & 1) * 8) * 2);
                uint32_t vh[4];
                ldsm_x4_t(vh, br);
#pragma unroll
                for (int mt = 0; mt < 2; mt++) {
                    mma16816(o[mt][2 * ntp],     aH[mt], &vh[0]);
                    mma16816(o[mt][2 * ntp + 1], aH[mt], &vh[2]);
                }
            }
        }
        __syncthreads();
    }

    // ---- epilogue: normalize, query mask, residual, fp32 store ----
#pragma unroll
    for (int mt = 0; mt < 2; mt++) {
        float qm0 = g_qmask[b * Ln + rowq[mt][0]];
        float qm1 = g_qmask[b * Ln + rowq[mt][1]];
        float f0 = qm0 / lsum[mt][0], f1 = qm1 / lsum[mt][1];
        size_t base0 = ((size_t)(b * Ln + rowq[mt][0])) * Dn + h * 64;
        size_t base1 = ((size_t)(b * Ln + rowq[mt][1])) * Dn + h * 64;
#pragma unroll
        for (int nt = 0; nt < 8; nt++) {
            int d = nt * 8 + c2;
            float2 r0v = *(const float2*)(queries + base0 + d);
            float2 r1v = *(const float2*)(queries + base1 + d);
            float2 o0, o1;
            o0.x = o[mt][nt][0] * f0 + r0v.x; o0.y = o[mt][nt][1] * f0 + r0v.y;
            o1.x = o[mt][nt][2] * f1 + r1v.x; o1.y = o[mt][nt][3] * f1 + r1v.y;
            *(float2*)(out + base0 + d) = o0;
            *(float2*)(out + base1 + d) = o1;
        }
    }
}

// ---------------------------------------------------------------------------
extern "C" void kernel_launch(void* const* d_in, const int* in_sizes, int n_in,
                              void* d_out, int out_size) {
    (void)in_sizes; (void)n_in; (void)out_size;
    const float* queries = (const float*)d_in[0];
    const float* keys    = (const float*)d_in[1];
    const float* Wq = (const float*)d_in[2];
    const float* bq = (const float*)d_in[3];
    const float* Wk = (const float*)d_in[4];
    const float* bk = (const float*)d_in[5];
    const float* Wv = (const float*)d_in[6];
    const float* bv = (const float*)d_in[7];
    float* out = (float*)d_out;

    cudaFuncSetAttribute(gemm_mma,
                         cudaFuncAttributeMaxDynamicSharedMemorySize, GEMM_SMEM);
    cudaFuncSetAttribute(attn_mma,
                         cudaFuncAttributeMaxDynamicSharedMemorySize, ATTN_SMEM);

    // 1) fused fp16 conversion + padding masks
    cvt_all<<<8384, 256>>>(queries, keys, Wq, Wk, Wv);

    // 2) QKV projections — all single-MMA fp16
    gemm_mma<<<dim3(4, 128, 3), 256, GEMM_SMEM>>>(bq, bk, bv);

    // 3) tensor-core attention + residual (S 1-MMA, PV 1-MMA)
    attn_mma<<<dim3(8, 8, 32), 128, ATTN_SMEM>>>(queries, out);
}

// round 15
// speedup vs baseline: 1.8269x; 1.0175x over previous
#include <cuda_runtime.h>
#include <cuda_fp16.h>
#include <math.h>
#include <cstdint>

// Problem dims (fixed by reference)
#define Bn  32
#define Ln  1024
#define Dn  512
#define Hn  8
#define DHn 64

#define NEGC (-4294967295.0f)   // -2^32 + 1, matches reference padding value
#define LOG2E 1.4426950408889634f

// ---------------------------------------------------------------------------
// Scratch (allocation-free rule: static __device__ globals)
// ---------------------------------------------------------------------------
__device__ float g_kmask[Bn * Ln];
__device__ float g_qmask[Bn * Ln];

#define NELEM_A ((size_t)Bn * Ln * Dn)      // 16,777,216
#define NELEM_W ((size_t)Dn * Dn)           // 262,144
__device__ __half g_qcv[NELEM_A];
__device__ __half g_kcv[NELEM_A];
__device__ __half g_wcv[3][NELEM_W];

// Projected Q/K/V, fp16, head-major [b][h][l][64].
// z: 0 = Q (pre-scaled by log2e/8 for base-2 softmax), 1 = K, 2 = V
__device__ __half g_prj[3][NELEM_A];

// ---------------------------------------------------------------------------
// PTX helpers (sm_80-baseline only — tcgen05 does NOT assemble at .target
// sm_103 in this harness)
// ---------------------------------------------------------------------------
__device__ __forceinline__ uint32_t smem_u32(const void* p) {
    uint32_t a;
    asm("{ .reg .u64 t; cvta.to.shared.u64 t, %1; cvt.u32.u64 %0, t; }"
        : "=r"(a) : "l"(p));
    return a;
}
__device__ __forceinline__ void cp16(uint32_t dst, const void* src) {
    asm volatile("cp.async.cg.shared.global [%0], [%1], 16;\n"
                 :: "r"(dst), "l"(src) : "memory");
}
#define CP_COMMIT() asm volatile("cp.async.commit_group;\n" ::: "memory")

__device__ __forceinline__ void ldsm_x4(uint32_t* r, uint32_t addr) {
    asm volatile("ldmatrix.sync.aligned.m8n8.x4.shared.b16 {%0,%1,%2,%3}, [%4];"
                 : "=r"(r[0]), "=r"(r[1]), "=r"(r[2]), "=r"(r[3]) : "r"(addr));
}
__device__ __forceinline__ void ldsm_x4_t(uint32_t* r, uint32_t addr) {
    asm volatile("ldmatrix.sync.aligned.m8n8.x4.trans.shared.b16 {%0,%1,%2,%3}, [%4];"
                 : "=r"(r[0]), "=r"(r[1]), "=r"(r[2]), "=r"(r[3]) : "r"(addr));
}
__device__ __forceinline__ void mma16816(float* d, const uint32_t* a, const uint32_t* b) {
    asm volatile(
        "mma.sync.aligned.m16n8k16.row.col.f32.f16.f16.f32 "
        "{%0,%1,%2,%3}, {%4,%5,%6,%7}, {%8,%9}, {%0,%1,%2,%3};"
        : "+f"(d[0]), "+f"(d[1]), "+f"(d[2]), "+f"(d[3])
        : "r"(a[0]), "r"(a[1]), "r"(a[2]), "r"(a[3]), "r"(b[0]), "r"(b[1]));
}
__device__ __forceinline__ uint32_t pack_h2(float a, float b) {
    __half2 t = __floats2half2_rn(a, b);
    return *(uint32_t*)&t;
}
__device__ __forceinline__ float ex2(float x) {
    float y;
    asm("ex2.approx.f32 %0, %1;" : "=f"(y) : "f"(x));
    return y;
}
// Packed fp16x2 base-2 exponential: one MUFU op for two elements.
__device__ __forceinline__ uint32_t ex2_h2(uint32_t x) {
    asm("ex2.approx.f16x2 %0, %0;" : "+r"(x));
    return x;
}

// ---------------------------------------------------------------------------
// Fused conversion (fp32 -> fp16) + padding masks. One warp per 512-elem row.
// ---------------------------------------------------------------------------
__global__ void __launch_bounds__(256) cvt_all(const float* __restrict__ q,
                                               const float* __restrict__ k,
                                               const float* __restrict__ Wq,
                                               const float* __restrict__ Wk,
                                               const float* __restrict__ Wv) {
    int w = blockIdx.x * 8 + (threadIdx.x >> 5);
    int lane = threadIdx.x & 31;
    const float* src;
    __half* dst;
    float* maskp = nullptr;
    if (w < 65536) {
        int row = w & 32767;
        size_t off = (size_t)row * Dn;
        if (w < 32768) {
            src = q + off; dst = g_qcv + off; maskp = g_qmask + row;
        } else {
            src = k + off; dst = g_kcv + off; maskp = g_kmask + row;
        }
    } else {
        int r = w - 65536;
        int z = r >> 9, row = r & 511;
        size_t off = (size_t)row * Dn;
        src = (z == 0 ? Wq : (z == 1 ? Wk : Wv)) + off;
        dst = g_wcv[z] + off;
    }
    float s = 0.f;
#pragma unroll
    for (int i = 0; i < 4; i++) {
        int f = lane + 32 * i;
        float4 v = ((const float4*)src)[f];
        s += (v.x + v.y) + (v.z + v.w);
        ((__half2*)dst)[2 * f + 0] = __floats2half2_rn(v.x, v.y);
        ((__half2*)dst)[2 * f + 1] = __floats2half2_rn(v.z, v.w);
    }
    if (maskp) {
#pragma unroll
        for (int o = 16; o; o >>= 1) s += __shfl_xor_sync(0xffffffffu, s, o);
        if (lane == 0) *maskp = (s != 0.0f) ? 1.0f : 0.0f;
    }
}

// ---------------------------------------------------------------------------
// fp16 GEMM (mma.sync): proj_z = A_z @ W_z^T + bias_z -> fp16, head-major
// [b][h][l][64]; Q pre-scaled by log2e/8.
// CTA tile 256x128, 8 warps, warp tile 64x64, K chunks of 32, 3-stage cp.async.
// ---------------------------------------------------------------------------
#define MATA   20480                 // 256 rows * 80B
#define MATW   10240                 // 128 rows * 80B
#define STAGE_B (MATA + MATW)          // 30720
#define GEMM_SMEM (3 * STAGE_B)        // 92160

__device__ __forceinline__ void load_stage(uint32_t st,
                                           const __half* A, const __half* W,
                                           int bm, int bn, int kc, int tid) {
#pragma unroll
    for (int i = 0; i < 4; i++) {
        int idx = tid + 256 * i;            // 0..1023
        int row = idx >> 2, q4 = idx & 3;
        cp16(st + row * 80 + q4 * 16,
             A + (size_t)(bm + row) * Dn + kc * 32 + q4 * 8);
    }
#pragma unroll
    for (int i = 0; i < 2; i++) {
        int idx = tid + 256 * i;            // 0..511
        int row = idx >> 2, q4 = idx & 3;
        cp16(st + MATA + row * 80 + q4 * 16,
             W + (size_t)(bn + row) * Dn + kc * 32 + q4 * 8);
    }
    CP_COMMIT();
}

__global__ void __launch_bounds__(256, 1) gemm_mma(const float* __restrict__ bq,
                                                   const float* __restrict__ bk,
                                                   const float* __restrict__ bv) {
    extern __shared__ char smem_raw[];
    uint32_t sbase = smem_u32(smem_raw);
    int tid = threadIdx.x;
    int wid = tid >> 5, lane = tid & 31;
    int wm = wid & 3;
    int wn = wid >> 2;
    int z = blockIdx.z;
    int bn = blockIdx.x * 128;
    int bm = blockIdx.y * 256;

    const __half* A = (z == 0) ? g_qcv : g_kcv;
    const __half* W = g_wcv[z];
    const float* bias = (z == 0) ? bq : (z == 1 ? bk : bv);
    float scale = (z == 0) ? (0.125f * LOG2E) : 1.0f;
    __half* O = g_prj[z];

    float acc[4][8][4];
#pragma unroll
    for (int mt = 0; mt < 4; mt++)
#pragma unroll
        for (int nt = 0; nt < 8; nt++)
#pragma unroll
            for (int e = 0; e < 4; e++) acc[mt][nt][e] = 0.f;

    int a_row = lane & 15;
    int a_koff = (lane >> 4) * 16;
    int g = lane >> 3;
    int b_nadd = ((g >> 1) & 1) * 8 + (lane & 7);
    int b_kadd = (g & 1) * 8;

    load_stage(sbase, A, W, bm, bn, 0, tid);
    load_stage(sbase + STAGE_B, A, W, bm, bn, 1, tid);

#pragma unroll 1
    for (int s = 0; s < 16; s++) {
        if (s < 15) {
            asm volatile("cp.async.wait_group 1;\n" ::: "memory");
        } else {
            asm volatile("cp.async.wait_group 0;\n" ::: "memory");
        }
        __syncthreads();
        if (s + 2 < 16) {
            load_stage(sbase + (uint32_t)((s + 2) % 3) * STAGE_B,
                       A, W, bm, bn, s + 2, tid);
        }
        uint32_t st = sbase + (uint32_t)(s % 3) * STAGE_B;

#pragma unroll
        for (int ks = 0; ks < 32; ks += 16) {
            uint32_t aF[4][4], bF[8][2];
#pragma unroll
            for (int mt = 0; mt < 4; mt++) {
                uint32_t ar = st + (uint32_t)((wm * 64 + mt * 16 + a_row) * 80)
                            + a_koff + ks * 2;
                ldsm_x4(aF[mt], ar);
            }
#pragma unroll
            for (int ntp = 0; ntp < 4; ntp++) {
                uint32_t br = st + MATA
                            + (uint32_t)((wn * 64 + ntp * 16 + b_nadd) * 80)
                            + (ks + b_kadd) * 2;
                uint32_t t0[4];
                ldsm_x4(t0, br);
                bF[2 * ntp][0] = t0[0]; bF[2 * ntp][1] = t0[1];
                bF[2 * ntp + 1][0] = t0[2]; bF[2 * ntp + 1][1] = t0[3];
            }
#pragma unroll
            for (int mt = 0; mt < 4; mt++)
#pragma unroll
                for (int nt = 0; nt < 8; nt++)
                    mma16816(acc[mt][nt], aF[mt], bF[nt]);
        }
        __syncthreads();
    }

    // Epilogue: bias, scale, fp16 store (head-major)
    int r = lane >> 2, c2 = (lane & 3) * 2;
#pragma unroll
    for (int mt = 0; mt < 4; mt++) {
#pragma unroll
        for (int nt = 0; nt < 8; nt++) {
            int col = bn + wn * 64 + nt * 8 + c2;
            float2 bb = *(const float2*)(bias + col);
            int hh = col >> 6, dd = col & 63;
#pragma unroll
            for (int half = 0; half < 2; half++) {
                int row = bm + wm * 64 + mt * 16 + r + half * 8;
                int bb_i = row >> 10, ll = row & 1023;
                size_t dst = ((size_t)((bb_i * Hn + hh) * Ln + ll)) * 64 + dd;
                float v0 = (acc[mt][nt][2 * half + 0] + bb.x) * scale;
                float v1 = (acc[mt][nt][2 * half + 1] + bb.y) * scale;
                *(__half2*)(O + dst) = __floats2half2_rn(v0, v1);
            }
        }
    }
}

// ---------------------------------------------------------------------------
// Tensor-core causal flash attention — pure fp16, packed-fp16 softmax exp.
// S = Q K^T: 1 MMA. P = ex2.approx.f16x2(S - m) — one MUFU per 2 elements,
// result IS the fp16 A-fragment. lsum accumulated (fp32) from the SAME
// quantized P values, so quantization bias cancels in O/lsum.
// CTA: 128 q-rows per (b,h); 4 warps x 32 rows; K tiles of 64 double-buffered;
// qt descending; 2 CTAs/SM.
// ---------------------------------------------------------------------------
#define ROWB 144                       // 72 fp16 per row
#define MATB (64 * ROWB)               // 9216
#define STG  (2 * MATB)                // 18432 (K, V)
#define KMOFF (2 * STG)                // 36864: kmask staging (2 x 256B)
#define QOFF (KMOFF + 512)             // 37376
#define ATTN_SMEM (QOFF + 128 * ROWB)  // 55808

__global__ void __launch_bounds__(128, 2) attn_mma(const float* __restrict__ queries,
                                                   float* __restrict__ out) {
    extern __shared__ char smraw[];
    uint32_t sb = smem_u32(smraw);
    int tid = threadIdx.x, wid = tid >> 5, lane = tid & 31;
    int qt = (int)gridDim.x - 1 - (int)blockIdx.x;   // heavy tiles first
    int h = blockIdx.y, b = blockIdx.z;
    int bh = b * Hn + h;
    int wq0 = wid * 32;

    const __half* Qp = g_prj[0] + (size_t)bh * Ln * 64;
    const __half* Kp = g_prj[1] + (size_t)bh * Ln * 64;
    const __half* Vp = g_prj[2] + (size_t)bh * Ln * 64;

    // ---- Q tile into dedicated SMEM ----
#pragma unroll
    for (int i = 0; i < 8; i++) {
        int idx = tid + 128 * i;          // 0..1023
        int row = idx >> 3, ch = idx & 7;
        cp16(sb + QOFF + row * ROWB + ch * 16,
             Qp + (size_t)(qt * 128 + row) * 64 + ch * 8);
    }
    CP_COMMIT();

    float o[2][8][4];
#pragma unroll
    for (int mt = 0; mt < 2; mt++)
#pragma unroll
        for (int nt = 0; nt < 8; nt++)
#pragma unroll
            for (int e = 0; e < 4; e++) o[mt][nt][e] = 0.f;
    float mrow[2][2], lsum[2][2];
#pragma unroll
    for (int mt = 0; mt < 2; mt++) {
        mrow[mt][0] = -INFINITY; mrow[mt][1] = -INFINITY;
        lsum[mt][0] = 0.f;       lsum[mt][1] = 0.f;
    }

    int ntk = 2 * qt + 2;

    auto load_kv = [&](int kt2) {
        uint32_t st = sb + (uint32_t)(kt2 & 1) * STG;
        int kg0 = kt2 * 64;
        const __half* srcs[2] = {Kp, Vp};
#pragma unroll
        for (int m = 0; m < 2; m++) {
#pragma unroll
            for (int i = 0; i < 4; i++) {
                int idx = tid + 128 * i;   // 0..511
                int row = idx >> 3, ch = idx & 7;
                cp16(st + m * MATB + row * ROWB + ch * 16,
                     srcs[m] + (size_t)(kg0 + row) * 64 + ch * 8);
            }
        }
        if (tid < 16)
            cp16(sb + KMOFF + (uint32_t)(kt2 & 1) * 256 + tid * 16,
                 g_kmask + b * Ln + kg0 + tid * 4);
        CP_COMMIT();
    };

    load_kv(0);

    int c2 = (lane & 3) * 2, rr = lane >> 2;
    int rowq[2][2];
#pragma unroll
    for (int mt = 0; mt < 2; mt++) {
        rowq[mt][0] = qt * 128 + wq0 + mt * 16 + rr;
        rowq[mt][1] = rowq[mt][0] + 8;
    }

#pragma unroll 1
    for (int kt = 0; kt < ntk; kt++) {
        if (kt + 1 < ntk) {
            load_kv(kt + 1);
            asm volatile("cp.async.wait_group 1;\n" ::: "memory");
        } else {
            asm volatile("cp.async.wait_group 0;\n" ::: "memory");
        }
        __syncthreads();
        uint32_t st = sb + (uint32_t)(kt & 1) * STG;

        // ---- S = Q K^T  (1 MMA per fragment pair; base-2 domain) ----
        float s[2][8][4];
#pragma unroll
        for (int mt = 0; mt < 2; mt++)
#pragma unroll
            for (int nt = 0; nt < 8; nt++)
#pragma unroll
                for (int e = 0; e < 4; e++) s[mt][nt][e] = 0.f;

#pragma unroll
        for (int dk = 0; dk < 4; dk++) {
            uint32_t qf[2][4];
#pragma unroll
            for (int mt = 0; mt < 2; mt++) {
                uint32_t ar = sb + QOFF
                    + (uint32_t)((wq0 + mt * 16 + (lane & 15)) * ROWB)
                    + (uint32_t)((dk * 16 + (lane >> 4) * 8) * 2);
                ldsm_x4(qf[mt], ar);
            }
#pragma unroll
            for (int ntp = 0; ntp < 4; ntp++) {
                uint32_t br = st
                    + (uint32_t)((ntp * 16 + (lane & 7) + ((lane >> 4) & 1) * 8) * ROWB)
                    + (uint32_t)((dk * 16 + ((lane >> 3) & 1) * 8) * 2);
                uint32_t th[4];
                ldsm_x4(th, br);
#pragma unroll
                for (int mt = 0; mt < 2; mt++) {
                    mma16816(s[mt][2 * ntp],     qf[mt], &th[0]);
                    mma16816(s[mt][2 * ntp + 1], qf[mt], &th[2]);
                }
            }
        }

        // ---- masks ----
        const float* kmp = (const float*)(smraw + KMOFF + (kt & 1) * 256);
        int kbase = kt * 64;
#pragma unroll
        for (int nt = 0; nt < 8; nt++) {
            int col = kbase + nt * 8 + c2;
            float km0 = kmp[nt * 8 + c2];
            float km1 = kmp[nt * 8 + c2 + 1];
#pragma unroll
            for (int mt = 0; mt < 2; mt++) {
                if (km0 == 0.f || col > rowq[mt][0])     s[mt][nt][0] = NEGC;
                if (km1 == 0.f || col + 1 > rowq[mt][0]) s[mt][nt][1] = NEGC;
                if (km0 == 0.f || col > rowq[mt][1])     s[mt][nt][2] = NEGC;
                if (km1 == 0.f || col + 1 > rowq[mt][1]) s[mt][nt][3] = NEGC;
            }
        }

        // ---- online softmax (base-2, packed fp16 ex2) ----
        uint32_t pP[2][8][2];          // packed fp16 P (A-fragment halves)
#pragma unroll
        for (int mt = 0; mt < 2; mt++) {
            float mx0 = -INFINITY, mx1 = -INFINITY;
#pragma unroll
            for (int nt = 0; nt < 8; nt++) {
                mx0 = fmaxf(mx0, fmaxf(s[mt][nt][0], s[mt][nt][1]));
                mx1 = fmaxf(mx1, fmaxf(s[mt][nt][2], s[mt][nt][3]));
            }
            mx0 = fmaxf(mx0, __shfl_xor_sync(0xffffffffu, mx0, 1));
            mx0 = fmaxf(mx0, __shfl_xor_sync(0xffffffffu, mx0, 2));
            mx1 = fmaxf(mx1, __shfl_xor_sync(0xffffffffu, mx1, 1));
            mx1 = fmaxf(mx1, __shfl_xor_sync(0xffffffffu, mx1, 2));
            float mn0 = fmaxf(mrow[mt][0], mx0), mn1 = fmaxf(mrow[mt][1], mx1);
            float corr0 = ex2(mrow[mt][0] - mn0), corr1 = ex2(mrow[mt][1] - mn1);
            mrow[mt][0] = mn0; mrow[mt][1] = mn1;

            float ps0 = 0.f, ps1 = 0.f;
#pragma unroll
            for (int nt = 0; nt < 8; nt++) {
                uint32_t h01 = ex2_h2(pack_h2(s[mt][nt][0] - mn0, s[mt][nt][1] - mn0));
                uint32_t h23 = ex2_h2(pack_h2(s[mt][nt][2] - mn1, s[mt][nt][3] - mn1));
                pP[mt][nt][0] = h01;
                pP[mt][nt][1] = h23;
                float2 f01 = __half22float2(*(__half2*)&h01);
                float2 f23 = __half22float2(*(__half2*)&h23);
                ps0 += f01.x + f01.y;
                ps1 += f23.x + f23.y;
            }
            ps0 += __shfl_xor_sync(0xffffffffu, ps0, 1);
            ps0 += __shfl_xor_sync(0xffffffffu, ps0, 2);
            ps1 += __shfl_xor_sync(0xffffffffu, ps1, 1);
            ps1 += __shfl_xor_sync(0xffffffffu, ps1, 2);
            lsum[mt][0] = lsum[mt][0] * corr0 + ps0;
            lsum[mt][1] = lsum[mt][1] * corr1 + ps1;
#pragma unroll
            for (int nt = 0; nt < 8; nt++) {
                o[mt][nt][0] *= corr0; o[mt][nt][1] *= corr0;
                o[mt][nt][2] *= corr1; o[mt][nt][3] *= corr1;
            }
        }

        // ---- O += P V  (1 MMA per fragment pair; P already packed) ----
#pragma unroll
        for (int ks = 0; ks < 4; ks++) {
            uint32_t aH[2][4];
#pragma unroll
            for (int mt = 0; mt < 2; mt++) {
                aH[mt][0] = pP[mt][2 * ks][0];
                aH[mt][1] = pP[mt][2 * ks][1];
                aH[mt][2] = pP[mt][2 * ks + 1][0];
                aH[mt][3] = pP[mt][2 * ks + 1][1];
            }
#pragma unroll
            for (int ntp = 0; ntp < 4; ntp++) {
                uint32_t br = st + MATB
                    + (uint32_t)((ks * 16 + (lane & 7) + ((lane >> 3) & 1) * 8) * ROWB)
                    + (uint32_t)((ntp * 16 + ((lane >> 4) & 1) * 8) * 2);
                uint32_t vh[4];
                ldsm_x4_t(vh, br);
#pragma unroll
                for (int mt = 0; mt < 2; mt++) {
                    mma16816(o[mt][2 * ntp],     aH[mt], &vh[0]);
                    mma16816(o[mt][2 * ntp + 1], aH[mt], &vh[2]);
                }
            }
        }
        __syncthreads();
    }

    // ---- epilogue: normalize, query mask, residual, fp32 store ----
#pragma unroll
    for (int mt = 0; mt < 2; mt++) {
        float qm0 = g_qmask[b * Ln + rowq[mt][0]];
        float qm1 = g_qmask[b * Ln + rowq[mt][1]];
        float f0 = qm0 / lsum[mt][0], f1 = qm1 / lsum[mt][1];
        size_t base0 = ((size_t)(b * Ln + rowq[mt][0])) * Dn + h * 64;
        size_t base1 = ((size_t)(b * Ln + rowq[mt][1])) * Dn + h * 64;
#pragma unroll
        for (int nt = 0; nt < 8; nt++) {
            int d = nt * 8 + c2;
            float2 r0v = *(const float2*)(queries + base0 + d);
            float2 r1v = *(const float2*)(queries + base1 + d);
            float2 o0, o1;
            o0.x = o[mt][nt][0] * f0 + r0v.x; o0.y = o[mt][nt][1] * f0 + r0v.y;
            o1.x = o[mt][nt][2] * f1 + r1v.x; o1.y = o[mt][nt][3] * f1 + r1v.y;
            *(float2*)(out + base0 + d) = o0;
            *(float2*)(out + base1 + d) = o1;
        }
    }
}

// ---------------------------------------------------------------------------
extern "C" void kernel_launch(void* const* d_in, const int* in_sizes, int n_in,
                              void* d_out, int out_size) {
    (void)in_sizes; (void)n_in; (void)out_size;
    const float* queries = (const float*)d_in[0];
    const float* keys    = (const float*)d_in[1];
    const float* Wq = (const float*)d_in[2];
    const float* bq = (const float*)d_in[3];
    const float* Wk = (const float*)d_in[4];
    const float* bk = (const float*)d_in[5];
    const float* Wv = (const float*)d_in[6];
    const float* bv = (const float*)d_in[7];
    float* out = (float*)d_out;

    cudaFuncSetAttribute(gemm_mma,
                         cudaFuncAttributeMaxDynamicSharedMemorySize, GEMM_SMEM);
    cudaFuncSetAttribute(attn_mma,
                         cudaFuncAttributeMaxDynamicSharedMemorySize, ATTN_SMEM);

    // 1) fused fp16 conversion + padding masks
    cvt_all<<<8384, 256>>>(queries, keys, Wq, Wk, Wv);

    // 2) QKV projections — single-MMA fp16, 3-stage pipeline
    gemm_mma<<<dim3(4, 128, 3), 256, GEMM_SMEM>>>(bq, bk, bv);

    // 3) tensor-core attention + residual (packed-fp16 softmax exp)
    attn_mma<<<dim3(8, 8, 32), 128, ATTN_SMEM>>>(queries, out);
}

// round 16
// speedup vs baseline: 1.8645x; 1.0206x over previous
#include <cuda_runtime.h>
#include <cuda_fp16.h>
#include <math.h>
#include <cstdint>

// Problem dims (fixed by reference)
#define Bn  32
#define Ln  1024
#define Dn  512
#define Hn  8
#define DHn 64

#define NEGC (-4294967295.0f)   // -2^32 + 1, matches reference padding value
#define LOG2E 1.4426950408889634f

// ---------------------------------------------------------------------------
// Scratch (allocation-free rule: static __device__ globals)
// ---------------------------------------------------------------------------
__device__ float g_kmask[Bn * Ln];
__device__ float g_qmask[Bn * Ln];

#define NELEM_A ((size_t)Bn * Ln * Dn)      // 16,777,216
#define NELEM_W ((size_t)Dn * Dn)           // 262,144
__device__ __half g_qcv[NELEM_A];
__device__ __half g_kcv[NELEM_A];
__device__ __half g_wcv[3][NELEM_W];

// Projected Q/K/V, fp16, head-major [b][h][l][64].
// z: 0 = Q (pre-scaled by log2e/8 for base-2 softmax), 1 = K, 2 = V
__device__ __half g_prj[3][NELEM_A];

// ---------------------------------------------------------------------------
// PTX helpers (sm_80-baseline only — tcgen05 does NOT assemble at .target
// sm_103 in this harness)
// ---------------------------------------------------------------------------
__device__ __forceinline__ uint32_t smem_u32(const void* p) {
    uint32_t a;
    asm("{ .reg .u64 t; cvta.to.shared.u64 t, %1; cvt.u32.u64 %0, t; }"
        : "=r"(a) : "l"(p));
    return a;
}
__device__ __forceinline__ void cp16(uint32_t dst, const void* src) {
    asm volatile("cp.async.cg.shared.global [%0], [%1], 16;\n"
                 :: "r"(dst), "l"(src) : "memory");
}
#define CP_COMMIT() asm volatile("cp.async.commit_group;\n" ::: "memory")

__device__ __forceinline__ void ldsm_x4(uint32_t* r, uint32_t addr) {
    asm volatile("ldmatrix.sync.aligned.m8n8.x4.shared.b16 {%0,%1,%2,%3}, [%4];"
                 : "=r"(r[0]), "=r"(r[1]), "=r"(r[2]), "=r"(r[3]) : "r"(addr));
}
__device__ __forceinline__ void ldsm_x4_t(uint32_t* r, uint32_t addr) {
    asm volatile("ldmatrix.sync.aligned.m8n8.x4.trans.shared.b16 {%0,%1,%2,%3}, [%4];"
                 : "=r"(r[0]), "=r"(r[1]), "=r"(r[2]), "=r"(r[3]) : "r"(addr));
}
__device__ __forceinline__ void mma16816(float* d, const uint32_t* a, const uint32_t* b) {
    asm volatile(
        "mma.sync.aligned.m16n8k16.row.col.f32.f16.f16.f32 "
        "{%0,%1,%2,%3}, {%4,%5,%6,%7}, {%8,%9}, {%0,%1,%2,%3};"
        : "+f"(d[0]), "+f"(d[1]), "+f"(d[2]), "+f"(d[3])
        : "r"(a[0]), "r"(a[1]), "r"(a[2]), "r"(a[3]), "r"(b[0]), "r"(b[1]));
}
__device__ __forceinline__ uint32_t pack_h2(float a, float b) {
    __half2 t = __floats2half2_rn(a, b);
    return *(uint32_t*)&t;
}
__device__ __forceinline__ float ex2(float x) {
    float y;
    asm("ex2.approx.f32 %0, %1;" : "=f"(y) : "f"(x));
    return y;
}
// Packed fp16x2 base-2 exponential: one MUFU op for two elements.
__device__ __forceinline__ uint32_t ex2_h2(uint32_t x) {
    asm("ex2.approx.f16x2 %0, %0;" : "+r"(x));
    return x;
}

// ---------------------------------------------------------------------------
// Fused conversion (fp32 -> fp16) + padding masks. One warp per 512-elem row.
// ---------------------------------------------------------------------------
__global__ void __launch_bounds__(256) cvt_all(const float* __restrict__ q,
                                               const float* __restrict__ k,
                                               const float* __restrict__ Wq,
                                               const float* __restrict__ Wk,
                                               const float* __restrict__ Wv) {
    int w = blockIdx.x * 8 + (threadIdx.x >> 5);
    int lane = threadIdx.x & 31;
    const float* src;
    __half* dst;
    float* maskp = nullptr;
    if (w < 65536) {
        int row = w & 32767;
        size_t off = (size_t)row * Dn;
        if (w < 32768) {
            src = q + off; dst = g_qcv + off; maskp = g_qmask + row;
        } else {
            src = k + off; dst = g_kcv + off; maskp = g_kmask + row;
        }
    } else {
        int r = w - 65536;
        int z = r >> 9, row = r & 511;
        size_t off = (size_t)row * Dn;
        src = (z == 0 ? Wq : (z == 1 ? Wk : Wv)) + off;
        dst = g_wcv[z] + off;
    }
    float s = 0.f;
#pragma unroll
    for (int i = 0; i < 4; i++) {
        int f = lane + 32 * i;
        float4 v = ((const float4*)src)[f];
        s += (v.x + v.y) + (v.z + v.w);
        ((__half2*)dst)[2 * f + 0] = __floats2half2_rn(v.x, v.y);
        ((__half2*)dst)[2 * f + 1] = __floats2half2_rn(v.z, v.w);
    }
    if (maskp) {
#pragma unroll
        for (int o = 16; o; o >>= 1) s += __shfl_xor_sync(0xffffffffu, s, o);
        if (lane == 0) *maskp = (s != 0.0f) ? 1.0f : 0.0f;
    }
}

// ---------------------------------------------------------------------------
// fp16 GEMM (mma.sync): proj_z = A_z @ W_z^T + bias_z -> fp16, head-major
// [b][h][l][64]; Q pre-scaled by log2e/8.
// CTA tile 256x128, 8 warps, warp tile 64x64, K chunks of 32, 3-stage cp.async.
// ---------------------------------------------------------------------------
#define MATA   20480                 // 256 rows * 80B
#define MATW   10240                 // 128 rows * 80B
#define STAGE_B (MATA + MATW)          // 30720
#define GEMM_SMEM (3 * STAGE_B)        // 92160

__device__ __forceinline__ void load_stage(uint32_t st,
                                           const __half* A, const __half* W,
                                           int bm, int bn, int kc, int tid) {
#pragma unroll
    for (int i = 0; i < 4; i++) {
        int idx = tid + 256 * i;            // 0..1023
        int row = idx >> 2, q4 = idx & 3;
        cp16(st + row * 80 + q4 * 16,
             A + (size_t)(bm + row) * Dn + kc * 32 + q4 * 8);
    }
#pragma unroll
    for (int i = 0; i < 2; i++) {
        int idx = tid + 256 * i;            // 0..511
        int row = idx >> 2, q4 = idx & 3;
        cp16(st + MATA + row * 80 + q4 * 16,
             W + (size_t)(bn + row) * Dn + kc * 32 + q4 * 8);
    }
    CP_COMMIT();
}

__global__ void __launch_bounds__(256, 1) gemm_mma(const float* __restrict__ bq,
                                                   const float* __restrict__ bk,
                                                   const float* __restrict__ bv) {
    extern __shared__ char smem_raw[];
    uint32_t sbase = smem_u32(smem_raw);
    int tid = threadIdx.x;
    int wid = tid >> 5, lane = tid & 31;
    int wm = wid & 3;
    int wn = wid >> 2;
    int z = blockIdx.z;
    int bn = blockIdx.x * 128;
    int bm = blockIdx.y * 256;

    const __half* A = (z == 0) ? g_qcv : g_kcv;
    const __half* W = g_wcv[z];
    const float* bias = (z == 0) ? bq : (z == 1 ? bk : bv);
    float scale = (z == 0) ? (0.125f * LOG2E) : 1.0f;
    __half* O = g_prj[z];

    float acc[4][8][4];
#pragma unroll
    for (int mt = 0; mt < 4; mt++)
#pragma unroll
        for (int nt = 0; nt < 8; nt++)
#pragma unroll
            for (int e = 0; e < 4; e++) acc[mt][nt][e] = 0.f;

    int a_row = lane & 15;
    int a_koff = (lane >> 4) * 16;
    int g = lane >> 3;
    int b_nadd = ((g >> 1) & 1) * 8 + (lane & 7);
    int b_kadd = (g & 1) * 8;

    load_stage(sbase, A, W, bm, bn, 0, tid);
    load_stage(sbase + STAGE_B, A, W, bm, bn, 1, tid);

#pragma unroll 1
    for (int s = 0; s < 16; s++) {
        if (s < 15) {
            asm volatile("cp.async.wait_group 1;\n" ::: "memory");
        } else {
            asm volatile("cp.async.wait_group 0;\n" ::: "memory");
        }
        __syncthreads();
        if (s + 2 < 16) {
            load_stage(sbase + (uint32_t)((s + 2) % 3) * STAGE_B,
                       A, W, bm, bn, s + 2, tid);
        }
        uint32_t st = sbase + (uint32_t)(s % 3) * STAGE_B;

#pragma unroll
        for (int ks = 0; ks < 32; ks += 16) {
            uint32_t aF[4][4], bF[8][2];
#pragma unroll
            for (int mt = 0; mt < 4; mt++) {
                uint32_t ar = st + (uint32_t)((wm * 64 + mt * 16 + a_row) * 80)
                            + a_koff + ks * 2;
                ldsm_x4(aF[mt], ar);
            }
#pragma unroll
            for (int ntp = 0; ntp < 4; ntp++) {
                uint32_t br = st + MATA
                            + (uint32_t)((wn * 64 + ntp * 16 + b_nadd) * 80)
                            + (ks + b_kadd) * 2;
                uint32_t t0[4];
                ldsm_x4(t0, br);
                bF[2 * ntp][0] = t0[0]; bF[2 * ntp][1] = t0[1];
                bF[2 * ntp + 1][0] = t0[2]; bF[2 * ntp + 1][1] = t0[3];
            }
#pragma unroll
            for (int mt = 0; mt < 4; mt++)
#pragma unroll
                for (int nt = 0; nt < 8; nt++)
                    mma16816(acc[mt][nt], aF[mt], bF[nt]);
        }
        __syncthreads();
    }

    // Epilogue: bias, scale, fp16 store (head-major)
    int r = lane >> 2, c2 = (lane & 3) * 2;
#pragma unroll
    for (int mt = 0; mt < 4; mt++) {
#pragma unroll
        for (int nt = 0; nt < 8; nt++) {
            int col = bn + wn * 64 + nt * 8 + c2;
            float2 bb = *(const float2*)(bias + col);
            int hh = col >> 6, dd = col & 63;
#pragma unroll
            for (int half = 0; half < 2; half++) {
                int row = bm + wm * 64 + mt * 16 + r + half * 8;
                int bb_i = row >> 10, ll = row & 1023;
                size_t dst = ((size_t)((bb_i * Hn + hh) * Ln + ll)) * 64 + dd;
                float v0 = (acc[mt][nt][2 * half + 0] + bb.x) * scale;
                float v1 = (acc[mt][nt][2 * half + 1] + bb.y) * scale;
                *(__half2*)(O + dst) = __floats2half2_rn(v0, v1);
            }
        }
    }
}

// ---------------------------------------------------------------------------
// Tensor-core causal flash attention — pure fp16, packed-fp16 softmax exp,
// dead-tile skipping:
//  * warp-tiles fully above the causal diagonal are exact no-ops -> skipped
//  * mask compare/select block skipped when tile is strictly below the
//    diagonal AND all keys valid (checked via __all_sync on staged kmask)
// CTA: 128 q-rows per (b,h); 4 warps x 32 rows; K tiles of 64 double-buffered;
// qt descending; 2 CTAs/SM.
// ---------------------------------------------------------------------------
#define ROWB 144                       // 72 fp16 per row
#define MATB (64 * ROWB)               // 9216
#define STG  (2 * MATB)                // 18432 (K, V)
#define KMOFF (2 * STG)                // 36864: kmask staging (2 x 256B)
#define QOFF (KMOFF + 512)             // 37376
#define ATTN_SMEM (QOFF + 128 * ROWB)  // 55808

__global__ void __launch_bounds__(128, 2) attn_mma(const float* __restrict__ queries,
                                                   float* __restrict__ out) {
    extern __shared__ char smraw[];
    uint32_t sb = smem_u32(smraw);
    int tid = threadIdx.x, wid = tid >> 5, lane = tid & 31;
    int qt = (int)gridDim.x - 1 - (int)blockIdx.x;   // heavy tiles first
    int h = blockIdx.y, b = blockIdx.z;
    int bh = b * Hn + h;
    int wq0 = wid * 32;
    int wmin = qt * 128 + wq0;          // warp's lowest q row

    const __half* Qp = g_prj[0] + (size_t)bh * Ln * 64;
    const __half* Kp = g_prj[1] + (size_t)bh * Ln * 64;
    const __half* Vp = g_prj[2] + (size_t)bh * Ln * 64;

    // ---- Q tile into dedicated SMEM ----
#pragma unroll
    for (int i = 0; i < 8; i++) {
        int idx = tid + 128 * i;          // 0..1023
        int row = idx >> 3, ch = idx & 7;
        cp16(sb + QOFF + row * ROWB + ch * 16,
             Qp + (size_t)(qt * 128 + row) * 64 + ch * 8);
    }
    CP_COMMIT();

    float o[2][8][4];
#pragma unroll
    for (int mt = 0; mt < 2; mt++)
#pragma unroll
        for (int nt = 0; nt < 8; nt++)
#pragma unroll
            for (int e = 0; e < 4; e++) o[mt][nt][e] = 0.f;
    float mrow[2][2], lsum[2][2];
#pragma unroll
    for (int mt = 0; mt < 2; mt++) {
        mrow[mt][0] = -INFINITY; mrow[mt][1] = -INFINITY;
        lsum[mt][0] = 0.f;       lsum[mt][1] = 0.f;
    }

    int ntk = 2 * qt + 2;

    auto load_kv = [&](int kt2) {
        uint32_t st = sb + (uint32_t)(kt2 & 1) * STG;
        int kg0 = kt2 * 64;
        const __half* srcs[2] = {Kp, Vp};
#pragma unroll
        for (int m = 0; m < 2; m++) {
#pragma unroll
            for (int i = 0; i < 4; i++) {
                int idx = tid + 128 * i;   // 0..511
                int row = idx >> 3, ch = idx & 7;
                cp16(st + m * MATB + row * ROWB + ch * 16,
                     srcs[m] + (size_t)(kg0 + row) * 64 + ch * 8);
            }
        }
        if (tid < 16)
            cp16(sb + KMOFF + (uint32_t)(kt2 & 1) * 256 + tid * 16,
                 g_kmask + b * Ln + kg0 + tid * 4);
        CP_COMMIT();
    };

    load_kv(0);

    int c2 = (lane & 3) * 2, rr = lane >> 2;
    int rowq[2][2];
#pragma unroll
    for (int mt = 0; mt < 2; mt++) {
        rowq[mt][0] = qt * 128 + wq0 + mt * 16 + rr;
        rowq[mt][1] = rowq[mt][0] + 8;
    }

#pragma unroll 1
    for (int kt = 0; kt < ntk; kt++) {
        if (kt + 1 < ntk) {
            load_kv(kt + 1);
            asm volatile("cp.async.wait_group 1;\n" ::: "memory");
        } else {
            asm volatile("cp.async.wait_group 0;\n" ::: "memory");
        }
        __syncthreads();
        uint32_t st = sb + (uint32_t)(kt & 1) * STG;
        int kbase = kt * 64;

        // Warp-tile entirely above the causal diagonal: exact no-op
        // (P == 0, corr == 1, lsum/o unchanged). Skip all compute.
        if (kbase <= wmin + 31) {

        // ---- S = Q K^T  (1 MMA per fragment pair; base-2 domain) ----
        float s[2][8][4];
#pragma unroll
        for (int mt = 0; mt < 2; mt++)
#pragma unroll
            for (int nt = 0; nt < 8; nt++)
#pragma unroll
                for (int e = 0; e < 4; e++) s[mt][nt][e] = 0.f;

#pragma unroll
        for (int dk = 0; dk < 4; dk++) {
            uint32_t qf[2][4];
#pragma unroll
            for (int mt = 0; mt < 2; mt++) {
                uint32_t ar = sb + QOFF
                    + (uint32_t)((wq0 + mt * 16 + (lane & 15)) * ROWB)
                    + (uint32_t)((dk * 16 + (lane >> 4) * 8) * 2);
                ldsm_x4(qf[mt], ar);
            }
#pragma unroll
            for (int ntp = 0; ntp < 4; ntp++) {
                uint32_t br = st
                    + (uint32_t)((ntp * 16 + (lane & 7) + ((lane >> 4) & 1) * 8) * ROWB)
                    + (uint32_t)((dk * 16 + ((lane >> 3) & 1) * 8) * 2);
                uint32_t th[4];
                ldsm_x4(th, br);
#pragma unroll
                for (int mt = 0; mt < 2; mt++) {
                    mma16816(s[mt][2 * ntp],     qf[mt], &th[0]);
                    mma16816(s[mt][2 * ntp + 1], qf[mt], &th[2]);
                }
            }
        }

        // ---- masks (skipped when provably all-pass) ----
        const float* kmp = (const float*)(smraw + KMOFF + (kt & 1) * 256);
        bool lv = (kmp[lane] != 0.f) && (kmp[lane + 32] != 0.f);
        bool allvalid = __all_sync(0xffffffffu, lv);
        bool need_causal = (kbase + 63 > wmin);
        if (need_causal || !allvalid) {
            if (allvalid) {
                // causal only
#pragma unroll
                for (int nt = 0; nt < 8; nt++) {
                    int col = kbase + nt * 8 + c2;
#pragma unroll
                    for (int mt = 0; mt < 2; mt++) {
                        if (col > rowq[mt][0])     s[mt][nt][0] = NEGC;
                        if (col + 1 > rowq[mt][0]) s[mt][nt][1] = NEGC;
                        if (col > rowq[mt][1])     s[mt][nt][2] = NEGC;
                        if (col + 1 > rowq[mt][1]) s[mt][nt][3] = NEGC;
                    }
                }
            } else {
#pragma unroll
                for (int nt = 0; nt < 8; nt++) {
                    int col = kbase + nt * 8 + c2;
                    float km0 = kmp[nt * 8 + c2];
                    float km1 = kmp[nt * 8 + c2 + 1];
#pragma unroll
                    for (int mt = 0; mt < 2; mt++) {
                        if (km0 == 0.f || col > rowq[mt][0])     s[mt][nt][0] = NEGC;
                        if (km1 == 0.f || col + 1 > rowq[mt][0]) s[mt][nt][1] = NEGC;
                        if (km0 == 0.f || col > rowq[mt][1])     s[mt][nt][2] = NEGC;
                        if (km1 == 0.f || col + 1 > rowq[mt][1]) s[mt][nt][3] = NEGC;
                    }
                }
            }
        }

        // ---- online softmax (base-2, packed fp16 ex2) ----
        uint32_t pP[2][8][2];          // packed fp16 P (A-fragment halves)
#pragma unroll
        for (int mt = 0; mt < 2; mt++) {
            float mx0 = -INFINITY, mx1 = -INFINITY;
#pragma unroll
            for (int nt = 0; nt < 8; nt++) {
                mx0 = fmaxf(mx0, fmaxf(s[mt][nt][0], s[mt][nt][1]));
                mx1 = fmaxf(mx1, fmaxf(s[mt][nt][2], s[mt][nt][3]));
            }
            mx0 = fmaxf(mx0, __shfl_xor_sync(0xffffffffu, mx0, 1));
            mx0 = fmaxf(mx0, __shfl_xor_sync(0xffffffffu, mx0, 2));
            mx1 = fmaxf(mx1, __shfl_xor_sync(0xffffffffu, mx1, 1));
            mx1 = fmaxf(mx1, __shfl_xor_sync(0xffffffffu, mx1, 2));
            float mn0 = fmaxf(mrow[mt][0], mx0), mn1 = fmaxf(mrow[mt][1], mx1);
            float corr0 = ex2(mrow[mt][0] - mn0), corr1 = ex2(mrow[mt][1] - mn1);
            mrow[mt][0] = mn0; mrow[mt][1] = mn1;

            float ps0 = 0.f, ps1 = 0.f;
#pragma unroll
            for (int nt = 0; nt < 8; nt++) {
                uint32_t h01 = ex2_h2(pack_h2(s[mt][nt][0] - mn0, s[mt][nt][1] - mn0));
                uint32_t h23 = ex2_h2(pack_h2(s[mt][nt][2] - mn1, s[mt][nt][3] - mn1));
                pP[mt][nt][0] = h01;
                pP[mt][nt][1] = h23;
                float2 f01 = __half22float2(*(__half2*)&h01);
                float2 f23 = __half22float2(*(__half2*)&h23);
                ps0 += f01.x + f01.y;
                ps1 += f23.x + f23.y;
            }
            ps0 += __shfl_xor_sync(0xffffffffu, ps0, 1);
            ps0 += __shfl_xor_sync(0xffffffffu, ps0, 2);
            ps1 += __shfl_xor_sync(0xffffffffu, ps1, 1);
            ps1 += __shfl_xor_sync(0xffffffffu, ps1, 2);
            lsum[mt][0] = lsum[mt][0] * corr0 + ps0;
            lsum[mt][1] = lsum[mt][1] * corr1 + ps1;
#pragma unroll
            for (int nt = 0; nt < 8; nt++) {
                o[mt][nt][0] *= corr0; o[mt][nt][1] *= corr0;
                o[mt][nt][2] *= corr1; o[mt][nt][3] *= corr1;
            }
        }

        // ---- O += P V  (1 MMA per fragment pair; P already packed) ----
#pragma unroll
        for (int ks = 0; ks < 4; ks++) {
            uint32_t aH[2][4];
#pragma unroll
            for (int mt = 0; mt < 2; mt++) {
                aH[mt][0] = pP[mt][2 * ks][0];
                aH[mt][1] = pP[mt][2 * ks][1];
                aH[mt][2] = pP[mt][2 * ks + 1][0];
                aH[mt][3] = pP[mt][2 * ks + 1][1];
            }
#pragma unroll
            for (int ntp = 0; ntp < 4; ntp++) {
                uint32_t br = st + MATB
                    + (uint32_t)((ks * 16 + (lane & 7) + ((lane >> 3) & 1) * 8) * ROWB)
                    + (uint32_t)((ntp * 16 + ((lane >> 4) & 1) * 8) * 2);
                uint32_t vh[4];
                ldsm_x4_t(vh, br);
#pragma unroll
                for (int mt = 0; mt < 2; mt++) {
                    mma16816(o[mt][2 * ntp],     aH[mt], &vh[0]);
                    mma16816(o[mt][2 * ntp + 1], aH[mt], &vh[2]);
                }
            }
        }

        }   // end active warp-tile
        __syncthreads();
    }

    // ---- epilogue: normalize, query mask, residual, fp32 store ----
#pragma unroll
    for (int mt = 0; mt < 2; mt++) {
        float qm0 = g_qmask[b * Ln + rowq[mt][0]];
        float qm1 = g_qmask[b * Ln + rowq[mt][1]];
        float f0 = qm0 / lsum[mt][0], f1 = qm1 / lsum[mt][1];
        size_t base0 = ((size_t)(b * Ln + rowq[mt][0])) * Dn + h * 64;
        size_t base1 = ((size_t)(b * Ln + rowq[mt][1])) * Dn + h * 64;
#pragma unroll
        for (int nt = 0; nt < 8; nt++) {
            int d = nt * 8 + c2;
            float2 r0v = *(const float2*)(queries + base0 + d);
            float2 r1v = *(const float2*)(queries + base1 + d);
            float2 o0, o1;
            o0.x = o[mt][nt][0] * f0 + r0v.x; o0.y = o[mt][nt][1] * f0 + r0v.y;
            o1.x = o[mt][nt][2] * f1 + r1v.x; o1.y = o[mt][nt][3] * f1 + r1v.y;
            *(float2*)(out + base0 + d) = o0;
            *(float2*)(out + base1 + d) = o1;
        }
    }
}

// ---------------------------------------------------------------------------
extern "C" void kernel_launch(void* const* d_in, const int* in_sizes, int n_in,
                              void* d_out, int out_size) {
    (void)in_sizes; (void)n_in; (void)out_size;
    const float* queries = (const float*)d_in[0];
    const float* keys    = (const float*)d_in[1];
    const float* Wq = (const float*)d_in[2];
    const float* bq = (const float*)d_in[3];
    const float* Wk = (const float*)d_in[4];
    const float* bk = (const float*)d_in[5];
    const float* Wv = (const float*)d_in[6];
    const float* bv = (const float*)d_in[7];
    float* out = (float*)d_out;

    cudaFuncSetAttribute(gemm_mma,
                         cudaFuncAttributeMaxDynamicSharedMemorySize, GEMM_SMEM);
    cudaFuncSetAttribute(attn_mma,
                         cudaFuncAttributeMaxDynamicSharedMemorySize, ATTN_SMEM);

    // 1) fused fp16 conversion + padding masks
    cvt_all<<<8384, 256>>>(queries, keys, Wq, Wk, Wv);

    // 2) QKV projections — single-MMA fp16, 3-stage pipeline
    gemm_mma<<<dim3(4, 128, 3), 256, GEMM_SMEM>>>(bq, bk, bv);

    // 3) tensor-core attention + residual (dead-tile skipping)
    attn_mma<<<dim3(8, 8, 32), 128, ATTN_SMEM>>>(queries, out);
}

// round 17
// speedup vs baseline: 2.0890x; 1.1204x over previous
#include <cuda_runtime.h>
#include <cuda_fp16.h>
#include <math.h>
#include <cstdint>

// Problem dims (fixed by reference)
#define Bn  32
#define Ln  1024
#define Dn  512
#define Hn  8
#define DHn 64

#define NEGC (-4294967295.0f)   // -2^32 + 1, matches reference padding value
#define LOG2E 1.4426950408889634f

// ---------------------------------------------------------------------------
// Scratch (allocation-free rule: static __device__ globals)
// ---------------------------------------------------------------------------
__device__ float g_kmask[Bn * Ln];
__device__ float g_qmask[Bn * Ln];

#define NELEM_A ((size_t)Bn * Ln * Dn)      // 16,777,216
#define NELEM_W ((size_t)Dn * Dn)           // 262,144
__device__ __half g_qcv[NELEM_A];
__device__ __half g_kcv[NELEM_A];
__device__ __half g_wcv[3][NELEM_W];

// Projected Q/K/V, fp16, head-major [b][h][l][64].
// z: 0 = Q (pre-scaled by log2e/8 for base-2 softmax), 1 = K, 2 = V
__device__ __half g_prj[3][NELEM_A];

// ---------------------------------------------------------------------------
// PTX helpers (sm_80-baseline only — tcgen05 does NOT assemble at .target
// sm_103 in this harness)
// ---------------------------------------------------------------------------
__device__ __forceinline__ uint32_t smem_u32(const void* p) {
    uint32_t a;
    asm("{ .reg .u64 t; cvta.to.shared.u64 t, %1; cvt.u32.u64 %0, t; }"
        : "=r"(a) : "l"(p));
    return a;
}
__device__ __forceinline__ void cp16(uint32_t dst, const void* src) {
    asm volatile("cp.async.cg.shared.global [%0], [%1], 16;\n"
                 :: "r"(dst), "l"(src) : "memory");
}
#define CP_COMMIT() asm volatile("cp.async.commit_group;\n" ::: "memory")

__device__ __forceinline__ void ldsm_x4(uint32_t* r, uint32_t addr) {
    asm volatile("ldmatrix.sync.aligned.m8n8.x4.shared.b16 {%0,%1,%2,%3}, [%4];"
                 : "=r"(r[0]), "=r"(r[1]), "=r"(r[2]), "=r"(r[3]) : "r"(addr));
}
__device__ __forceinline__ void ldsm_x4_t(uint32_t* r, uint32_t addr) {
    asm volatile("ldmatrix.sync.aligned.m8n8.x4.trans.shared.b16 {%0,%1,%2,%3}, [%4];"
                 : "=r"(r[0]), "=r"(r[1]), "=r"(r[2]), "=r"(r[3]) : "r"(addr));
}
__device__ __forceinline__ void mma16816(float* d, const uint32_t* a, const uint32_t* b) {
    asm volatile(
        "mma.sync.aligned.m16n8k16.row.col.f32.f16.f16.f32 "
        "{%0,%1,%2,%3}, {%4,%5,%6,%7}, {%8,%9}, {%0,%1,%2,%3};"
        : "+f"(d[0]), "+f"(d[1]), "+f"(d[2]), "+f"(d[3])
        : "r"(a[0]), "r"(a[1]), "r"(a[2]), "r"(a[3]), "r"(b[0]), "r"(b[1]));
}
__device__ __forceinline__ uint32_t pack_h2(float a, float b) {
    __half2 t = __floats2half2_rn(a, b);
    return *(uint32_t*)&t;
}
__device__ __forceinline__ float ex2(float x) {
    float y;
    asm("ex2.approx.f32 %0, %1;" : "=f"(y) : "f"(x));
    return y;
}
// Packed fp16x2 base-2 exponential: one MUFU op for two elements.
__device__ __forceinline__ uint32_t ex2_h2(uint32_t x) {
    asm("ex2.approx.f16x2 %0, %0;" : "+r"(x));
    return x;
}

// ---------------------------------------------------------------------------
// Fused conversion (fp32 -> fp16) + padding masks. One warp per 512-elem row.
// ---------------------------------------------------------------------------
__global__ void __launch_bounds__(256) cvt_all(const float* __restrict__ q,
                                               const float* __restrict__ k,
                                               const float* __restrict__ Wq,
                                               const float* __restrict__ Wk,
                                               const float* __restrict__ Wv) {
    int w = blockIdx.x * 8 + (threadIdx.x >> 5);
    int lane = threadIdx.x & 31;
    const float* src;
    __half* dst;
    float* maskp = nullptr;
    if (w < 65536) {
        int row = w & 32767;
        size_t off = (size_t)row * Dn;
        if (w < 32768) {
            src = q + off; dst = g_qcv + off; maskp = g_qmask + row;
        } else {
            src = k + off; dst = g_kcv + off; maskp = g_kmask + row;
        }
    } else {
        int r = w - 65536;
        int z = r >> 9, row = r & 511;
        size_t off = (size_t)row * Dn;
        src = (z == 0 ? Wq : (z == 1 ? Wk : Wv)) + off;
        dst = g_wcv[z] + off;
    }
    float s = 0.f;
#pragma unroll
    for (int i = 0; i < 4; i++) {
        int f = lane + 32 * i;
        float4 v = ((const float4*)src)[f];
        s += (v.x + v.y) + (v.z + v.w);
        ((__half2*)dst)[2 * f + 0] = __floats2half2_rn(v.x, v.y);
        ((__half2*)dst)[2 * f + 1] = __floats2half2_rn(v.z, v.w);
    }
    if (maskp) {
#pragma unroll
        for (int o = 16; o; o >>= 1) s += __shfl_xor_sync(0xffffffffu, s, o);
        if (lane == 0) *maskp = (s != 0.0f) ? 1.0f : 0.0f;
    }
}

// ---------------------------------------------------------------------------
// fp16 GEMM (mma.sync): proj_z = A_z @ W_z^T + bias_z -> fp16, head-major
// [b][h][l][64]; Q pre-scaled by log2e/8.
// CTA tile 128x128, 8 warps (4 over M x 2 over N), warp tile 32x64,
// K chunks of 32, 3-stage cp.async, 2 CTAs/SM (bubble overlap).
// grid = (4, 256, 3).
// ---------------------------------------------------------------------------
#define GMAT   10240                 // 128 rows * 80B
#define STAGE_B (2 * GMAT)             // 20480 (A + W)
#define GEMM_SMEM (3 * STAGE_B)        // 61440

__device__ __forceinline__ void load_stage(uint32_t st,
                                           const __half* A, const __half* W,
                                           int bm, int bn, int kc, int tid) {
#pragma unroll
    for (int i = 0; i < 2; i++) {
        int idx = tid + 256 * i;            // 0..511
        int row = idx >> 2, q4 = idx & 3;
        cp16(st + row * 80 + q4 * 16,
             A + (size_t)(bm + row) * Dn + kc * 32 + q4 * 8);
    }
#pragma unroll
    for (int i = 0; i < 2; i++) {
        int idx = tid + 256 * i;            // 0..511
        int row = idx >> 2, q4 = idx & 3;
        cp16(st + GMAT + row * 80 + q4 * 16,
             W + (size_t)(bn + row) * Dn + kc * 32 + q4 * 8);
    }
    CP_COMMIT();
}

__global__ void __launch_bounds__(256, 2) gemm_mma(const float* __restrict__ bq,
                                                   const float* __restrict__ bk,
                                                   const float* __restrict__ bv) {
    extern __shared__ char smem_raw[];
    uint32_t sbase = smem_u32(smem_raw);
    int tid = threadIdx.x;
    int wid = tid >> 5, lane = tid & 31;
    int wm = wid & 3;                 // 4 warps over M (32 rows each)
    int wn = wid >> 2;                // 2 warps over N (64 cols each)
    int z = blockIdx.z;
    int bn = blockIdx.x * 128;
    int bm = blockIdx.y * 128;

    const __half* A = (z == 0) ? g_qcv : g_kcv;
    const __half* W = g_wcv[z];
    const float* bias = (z == 0) ? bq : (z == 1 ? bk : bv);
    float scale = (z == 0) ? (0.125f * LOG2E) : 1.0f;
    __half* O = g_prj[z];

    float acc[2][8][4];
#pragma unroll
    for (int mt = 0; mt < 2; mt++)
#pragma unroll
        for (int nt = 0; nt < 8; nt++)
#pragma unroll
            for (int e = 0; e < 4; e++) acc[mt][nt][e] = 0.f;

    int a_row = lane & 15;
    int a_koff = (lane >> 4) * 16;
    int g = lane >> 3;
    int b_nadd = ((g >> 1) & 1) * 8 + (lane & 7);
    int b_kadd = (g & 1) * 8;

    load_stage(sbase, A, W, bm, bn, 0, tid);
    load_stage(sbase + STAGE_B, A, W, bm, bn, 1, tid);

#pragma unroll 1
    for (int s = 0; s < 16; s++) {
        if (s < 15) {
            asm volatile("cp.async.wait_group 1;\n" ::: "memory");
        } else {
            asm volatile("cp.async.wait_group 0;\n" ::: "memory");
        }
        __syncthreads();
        if (s + 2 < 16) {
            load_stage(sbase + (uint32_t)((s + 2) % 3) * STAGE_B,
                       A, W, bm, bn, s + 2, tid);
        }
        uint32_t st = sbase + (uint32_t)(s % 3) * STAGE_B;

#pragma unroll
        for (int ks = 0; ks < 32; ks += 16) {
            uint32_t aF[2][4], bF[8][2];
#pragma unroll
            for (int mt = 0; mt < 2; mt++) {
                uint32_t ar = st + (uint32_t)((wm * 32 + mt * 16 + a_row) * 80)
                            + a_koff + ks * 2;
                ldsm_x4(aF[mt], ar);
            }
#pragma unroll
            for (int ntp = 0; ntp < 4; ntp++) {
                uint32_t br = st + GMAT
                            + (uint32_t)((wn * 64 + ntp * 16 + b_nadd) * 80)
                            + (ks + b_kadd) * 2;
                uint32_t t0[4];
                ldsm_x4(t0, br);
                bF[2 * ntp][0] = t0[0]; bF[2 * ntp][1] = t0[1];
                bF[2 * ntp + 1][0] = t0[2]; bF[2 * ntp + 1][1] = t0[3];
            }
#pragma unroll
            for (int mt = 0; mt < 2; mt++)
#pragma unroll
                for (int nt = 0; nt < 8; nt++)
                    mma16816(acc[mt][nt], aF[mt], bF[nt]);
        }
        __syncthreads();
    }

    // Epilogue: bias, scale, fp16 store (head-major)
    int r = lane >> 2, c2 = (lane & 3) * 2;
#pragma unroll
    for (int mt = 0; mt < 2; mt++) {
#pragma unroll
        for (int nt = 0; nt < 8; nt++) {
            int col = bn + wn * 64 + nt * 8 + c2;
            float2 bb = *(const float2*)(bias + col);
            int hh = col >> 6, dd = col & 63;
#pragma unroll
            for (int half = 0; half < 2; half++) {
                int row = bm + wm * 32 + mt * 16 + r + half * 8;
                int bb_i = row >> 10, ll = row & 1023;
                size_t dst = ((size_t)((bb_i * Hn + hh) * Ln + ll)) * 64 + dd;
                float v0 = (acc[mt][nt][2 * half + 0] + bb.x) * scale;
                float v1 = (acc[mt][nt][2 * half + 1] + bb.y) * scale;
                *(__half2*)(O + dst) = __floats2half2_rn(v0, v1);
            }
        }
    }
}

// ---------------------------------------------------------------------------
// Tensor-core causal flash attention — pure fp16, packed-fp16 softmax exp,
// dead-tile skipping, Q fragments register-resident (32 regs, loaded once).
// CTA: 128 q-rows per (b,h); 4 warps x 32 rows; K tiles of 64 double-buffered;
// qt descending; 2 CTAs/SM.
// ---------------------------------------------------------------------------
#define ROWB 144                       // 72 fp16 per row
#define MATB (64 * ROWB)               // 9216
#define STG  (2 * MATB)                // 18432 (K, V)
#define KMOFF (2 * STG)                // 36864: kmask staging (2 x 256B)
#define QOFF (KMOFF + 512)             // 37376
#define ATTN_SMEM (QOFF + 128 * ROWB)  // 55808

__global__ void __launch_bounds__(128, 2) attn_mma(const float* __restrict__ queries,
                                                   float* __restrict__ out) {
    extern __shared__ char smraw[];
    uint32_t sb = smem_u32(smraw);
    int tid = threadIdx.x, wid = tid >> 5, lane = tid & 31;
    int qt = (int)gridDim.x - 1 - (int)blockIdx.x;   // heavy tiles first
    int h = blockIdx.y, b = blockIdx.z;
    int bh = b * Hn + h;
    int wq0 = wid * 32;
    int wmin = qt * 128 + wq0;          // warp's lowest q row

    const __half* Qp = g_prj[0] + (size_t)bh * Ln * 64;
    const __half* Kp = g_prj[1] + (size_t)bh * Ln * 64;
    const __half* Vp = g_prj[2] + (size_t)bh * Ln * 64;

    // ---- stage Q tile (commit group 0) ----
#pragma unroll
    for (int i = 0; i < 8; i++) {
        int idx = tid + 128 * i;          // 0..1023
        int row = idx >> 3, ch = idx & 7;
        cp16(sb + QOFF + row * ROWB + ch * 16,
             Qp + (size_t)(qt * 128 + row) * 64 + ch * 8);
    }
    CP_COMMIT();

    auto load_kv = [&](int kt2) {
        uint32_t st = sb + (uint32_t)(kt2 & 1) * STG;
        int kg0 = kt2 * 64;
        const __half* srcs[2] = {Kp, Vp};
#pragma unroll
        for (int m = 0; m < 2; m++) {
#pragma unroll
            for (int i = 0; i < 4; i++) {
                int idx = tid + 128 * i;   // 0..511
                int row = idx >> 3, ch = idx & 7;
                cp16(st + m * MATB + row * ROWB + ch * 16,
                     srcs[m] + (size_t)(kg0 + row) * 64 + ch * 8);
            }
        }
        if (tid < 16)
            cp16(sb + KMOFF + (uint32_t)(kt2 & 1) * 256 + tid * 16,
                 g_kmask + b * Ln + kg0 + tid * 4);
        CP_COMMIT();
    };

    load_kv(0);   // commit group 1 (in flight while Q fragments load)

    // ---- wait for Q only, hoist Q fragments into registers ----
    asm volatile("cp.async.wait_group 1;\n" ::: "memory");
    __syncthreads();
    uint32_t qf[4][2][4];              // [dk][mt][frag] — 32 regs
#pragma unroll
    for (int dk = 0; dk < 4; dk++)
#pragma unroll
        for (int mt = 0; mt < 2; mt++) {
            uint32_t ar = sb + QOFF
                + (uint32_t)((wq0 + mt * 16 + (lane & 15)) * ROWB)
                + (uint32_t)((dk * 16 + (lane >> 4) * 8) * 2);
            ldsm_x4(qf[dk][mt], ar);
        }

    float o[2][8][4];
#pragma unroll
    for (int mt = 0; mt < 2; mt++)
#pragma unroll
        for (int nt = 0; nt < 8; nt++)
#pragma unroll
            for (int e = 0; e < 4; e++) o[mt][nt][e] = 0.f;
    float mrow[2][2], lsum[2][2];
#pragma unroll
    for (int mt = 0; mt < 2; mt++) {
        mrow[mt][0] = -INFINITY; mrow[mt][1] = -INFINITY;
        lsum[mt][0] = 0.f;       lsum[mt][1] = 0.f;
    }

    int ntk = 2 * qt + 2;
    int c2 = (lane & 3) * 2, rr = lane >> 2;
    int rowq[2][2];
#pragma unroll
    for (int mt = 0; mt < 2; mt++) {
        rowq[mt][0] = qt * 128 + wq0 + mt * 16 + rr;
        rowq[mt][1] = rowq[mt][0] + 8;
    }

#pragma unroll 1
    for (int kt = 0; kt < ntk; kt++) {
        if (kt + 1 < ntk) {
            load_kv(kt + 1);
            asm volatile("cp.async.wait_group 1;\n" ::: "memory");
        } else {
            asm volatile("cp.async.wait_group 0;\n" ::: "memory");
        }
        __syncthreads();
        uint32_t st = sb + (uint32_t)(kt & 1) * STG;
        int kbase = kt * 64;

        // Warp-tile entirely above the causal diagonal: exact no-op — skip.
        if (kbase <= wmin + 31) {

        // ---- S = Q K^T  (1 MMA per fragment pair; base-2 domain) ----
        float s[2][8][4];
#pragma unroll
        for (int mt = 0; mt < 2; mt++)
#pragma unroll
            for (int nt = 0; nt < 8; nt++)
#pragma unroll
                for (int e = 0; e < 4; e++) s[mt][nt][e] = 0.f;

#pragma unroll
        for (int dk = 0; dk < 4; dk++) {
#pragma unroll
            for (int ntp = 0; ntp < 4; ntp++) {
                uint32_t br = st
                    + (uint32_t)((ntp * 16 + (lane & 7) + ((lane >> 4) & 1) * 8) * ROWB)
                    + (uint32_t)((dk * 16 + ((lane >> 3) & 1) * 8) * 2);
                uint32_t th[4];
                ldsm_x4(th, br);
#pragma unroll
                for (int mt = 0; mt < 2; mt++) {
                    mma16816(s[mt][2 * ntp],     qf[dk][mt], &th[0]);
                    mma16816(s[mt][2 * ntp + 1], qf[dk][mt], &th[2]);
                }
            }
        }

        // ---- masks (skipped when provably all-pass) ----
        const float* kmp = (const float*)(smraw + KMOFF + (kt & 1) * 256);
        bool lv = (kmp[lane] != 0.f) && (kmp[lane + 32] != 0.f);
        bool allvalid = __all_sync(0xffffffffu, lv);
        bool need_causal = (kbase + 63 > wmin);
        if (need_causal || !allvalid) {
            if (allvalid) {
#pragma unroll
                for (int nt = 0; nt < 8; nt++) {
                    int col = kbase + nt * 8 + c2;
#pragma unroll
                    for (int mt = 0; mt < 2; mt++) {
                        if (col > rowq[mt][0])     s[mt][nt][0] = NEGC;
                        if (col + 1 > rowq[mt][0]) s[mt][nt][1] = NEGC;
                        if (col > rowq[mt][1])     s[mt][nt][2] = NEGC;
                        if (col + 1 > rowq[mt][1]) s[mt][nt][3] = NEGC;
                    }
                }
            } else {
#pragma unroll
                for (int nt = 0; nt < 8; nt++) {
                    int col = kbase + nt * 8 + c2;
                    float km0 = kmp[nt * 8 + c2];
                    float km1 = kmp[nt * 8 + c2 + 1];
#pragma unroll
                    for (int mt = 0; mt < 2; mt++) {
                        if (km0 == 0.f || col > rowq[mt][0])     s[mt][nt][0] = NEGC;
                        if (km1 == 0.f || col + 1 > rowq[mt][0]) s[mt][nt][1] = NEGC;
                        if (km0 == 0.f || col > rowq[mt][1])     s[mt][nt][2] = NEGC;
                        if (km1 == 0.f || col + 1 > rowq[mt][1]) s[mt][nt][3] = NEGC;
                    }
                }
            }
        }

        // ---- online softmax (base-2, packed fp16 ex2) ----
        uint32_t pP[2][8][2];
#pragma unroll
        for (int mt = 0; mt < 2; mt++) {
            float mx0 = -INFINITY, mx1 = -INFINITY;
#pragma unroll
            for (int nt = 0; nt < 8; nt++) {
                mx0 = fmaxf(mx0, fmaxf(s[mt][nt][0], s[mt][nt][1]));
                mx1 = fmaxf(mx1, fmaxf(s[mt][nt][2], s[mt][nt][3]));
            }
            mx0 = fmaxf(mx0, __shfl_xor_sync(0xffffffffu, mx0, 1));
            mx0 = fmaxf(mx0, __shfl_xor_sync(0xffffffffu, mx0, 2));
            mx1 = fmaxf(mx1, __shfl_xor_sync(0xffffffffu, mx1, 1));
            mx1 = fmaxf(mx1, __shfl_xor_sync(0xffffffffu, mx1, 2));
            float mn0 = fmaxf(mrow[mt][0], mx0), mn1 = fmaxf(mrow[mt][1], mx1);
            float corr0 = ex2(mrow[mt][0] - mn0), corr1 = ex2(mrow[mt][1] - mn1);
            mrow[mt][0] = mn0; mrow[mt][1] = mn1;

            float ps0 = 0.f, ps1 = 0.f;
#pragma unroll
            for (int nt = 0; nt < 8; nt++) {
                uint32_t h01 = ex2_h2(pack_h2(s[mt][nt][0] - mn0, s[mt][nt][1] - mn0));
                uint32_t h23 = ex2_h2(pack_h2(s[mt][nt][2] - mn1, s[mt][nt][3] - mn1));
                pP[mt][nt][0] = h01;
                pP[mt][nt][1] = h23;
                float2 f01 = __half22float2(*(__half2*)&h01);
                float2 f23 = __half22float2(*(__half2*)&h23);
                ps0 += f01.x + f01.y;
                ps1 += f23.x + f23.y;
            }
            ps0 += __shfl_xor_sync(0xffffffffu, ps0, 1);
            ps0 += __shfl_xor_sync(0xffffffffu, ps0, 2);
            ps1 += __shfl_xor_sync(0xffffffffu, ps1, 1);
            ps1 += __shfl_xor_sync(0xffffffffu, ps1, 2);
            lsum[mt][0] = lsum[mt][0] * corr0 + ps0;
            lsum[mt][1] = lsum[mt][1] * corr1 + ps1;
#pragma unroll
            for (int nt = 0; nt < 8; nt++) {
                o[mt][nt][0] *= corr0; o[mt][nt][1] *= corr0;
                o[mt][nt][2] *= corr1; o[mt][nt][3] *= corr1;
            }
        }

        // ---- O += P V  (1 MMA per fragment pair; P already packed) ----
#pragma unroll
        for (int ks = 0; ks < 4; ks++) {
            uint32_t aH[2][4];
#pragma unroll
            for (int mt = 0; mt < 2; mt++) {
                aH[mt][0] = pP[mt][2 * ks][0];
                aH[mt][1] = pP[mt][2 * ks][1];
                aH[mt][2] = pP[mt][2 * ks + 1][0];
                aH[mt][3] = pP[mt][2 * ks + 1][1];
            }
#pragma unroll
            for (int ntp = 0; ntp < 4; ntp++) {
                uint32_t br = st + MATB
                    + (uint32_t)((ks * 16 + (lane & 7) + ((lane >> 3) & 1) * 8) * ROWB)
                    + (uint32_t)((ntp * 16 + ((lane >> 4) & 1) * 8) * 2);
                uint32_t vh[4];
                ldsm_x4_t(vh, br);
#pragma unroll
                for (int mt = 0; mt < 2; mt++) {
                    mma16816(o[mt][2 * ntp],     aH[mt], &vh[0]);
                    mma16816(o[mt][2 * ntp + 1], aH[mt], &vh[2]);
                }
            }
        }

        }   // end active warp-tile
        __syncthreads();
    }

    // ---- epilogue: normalize, query mask, residual, fp32 store ----
#pragma unroll
    for (int mt = 0; mt < 2; mt++) {
        float qm0 = g_qmask[b * Ln + rowq[mt][0]];
        float qm1 = g_qmask[b * Ln + rowq[mt][1]];
        float f0 = qm0 / lsum[mt][0], f1 = qm1 / lsum[mt][1];
        size_t base0 = ((size_t)(b * Ln + rowq[mt][0])) * Dn + h * 64;
        size_t base1 = ((size_t)(b * Ln + rowq[mt][1])) * Dn + h * 64;
#pragma unroll
        for (int nt = 0; nt < 8; nt++) {
            int d = nt * 8 + c2;
            float2 r0v = *(const float2*)(queries + base0 + d);
            float2 r1v = *(const float2*)(queries + base1 + d);
            float2 o0, o1;
            o0.x = o[mt][nt][0] * f0 + r0v.x; o0.y = o[mt][nt][1] * f0 + r0v.y;
            o1.x = o[mt][nt][2] * f1 + r1v.x; o1.y = o[mt][nt][3] * f1 + r1v.y;
            *(float2*)(out + base0 + d) = o0;
            *(float2*)(out + base1 + d) = o1;
        }
    }
}

// ---------------------------------------------------------------------------
extern "C" void kernel_launch(void* const* d_in, const int* in_sizes, int n_in,
                              void* d_out, int out_size) {
    (void)in_sizes; (void)n_in; (void)out_size;
    const float* queries = (const float*)d_in[0];
    const float* keys    = (const float*)d_in[1];
    const float* Wq = (const float*)d_in[2];
    const float* bq = (const float*)d_in[3];
    const float* Wk = (const float*)d_in[4];
    const float* bk = (const float*)d_in[5];
    const float* Wv = (const float*)d_in[6];
    const float* bv = (const float*)d_in[7];
    float* out = (float*)d_out;

    cudaFuncSetAttribute(gemm_mma,
                         cudaFuncAttributeMaxDynamicSharedMemorySize, GEMM_SMEM);
    cudaFuncSetAttribute(attn_mma,
                         cudaFuncAttributeMaxDynamicSharedMemorySize, ATTN_SMEM);

    // 1) fused fp16 conversion + padding masks
    cvt_all<<<8384, 256>>>(queries, keys, Wq, Wk, Wv);

    // 2) QKV projections — 128x128 tiles, 2 CTAs/SM, 3-stage pipeline
    gemm_mma<<<dim3(4, 256, 3), 256, GEMM_SMEM>>>(bq, bk, bv);

    // 3) tensor-core attention + residual (Q register-resident, dead-tile skip)
    attn_mma<<<dim3(8, 8, 32), 128, ATTN_SMEM>>>(queries, out);
}